// round 9
// baseline (speedup 1.0000x reference)
#include <cuda_runtime.h>
#include <cuda_fp16.h>
#include <cstdint>

// ---------------- problem constants ----------------
#define BB    64
#define CIN   2048
#define COUT  32
#define HH    14
#define WW    14
#define HWSZ  196
#define REP   1024
#define FEAT  (CIN*COUT)   // 65536

// ---------------- conv tiling (fp16) ----------------
#define CV_QX      8                       // cin splits
#define CV_NCH     16                      // chunks per CTA (16 cin each)
#define CV_XSTR    264
#define CV_WSTR    40
#define CV_WTAP    (8*CV_WSTR)
#define CV_XS_U32  (8*CV_XSTR)
#define CV_WS_U32  (9*CV_WTAP)
#define CV_STAGE_U32 (CV_XS_U32+CV_WS_U32)
#define CONV_SMEM  (2*CV_STAGE_U32*4)      // 39936 B

// ---------------- einsum tiling (fp16, K=208) ----------------
#define EM_STRU    108
#define EM_SMEM    (96*EM_STRU*4)          // 41472 B

// ---------------- fc6 tiling (tf32, 4-stage pipeline) ----------------
#define FC6_KT     32
#define FC6_KPER   (FEAT/FC6_KT)           // 2048
#define FC6_KC     32
#define FC6_NCHUNK (FC6_KPER/FC6_KC)       // 64
#define F6_STR     36
#define A_FLOATS   (128*F6_STR)
#define B_FLOATS   (64*F6_STR)
#define STAGE_FLOATS (A_FLOATS+B_FLOATS)
#define FC6_NSTG   4
#define FC6_SMEM   (FC6_NSTG*STAGE_FLOATS*4)  // 110592 B

// ---------------- prep sections ----------------
#define NPA  ((size_t)BB*1024*256/256)     // 65536 blocks: conv canvas
#define NPB  ((size_t)BB*CIN*104/256)      // 53248 blocks: einsum x
#define NPC  (128*9*8*32/256)              // 1152  blocks: weights

// ---------------- scratch (device globals) ----------------
__device__ uint32_t g_xph[(size_t)BB*1024*256];   // conv x canvas half2
__device__ uint32_t g_xe[(size_t)BB*CIN*104];     // einsum x half2, K=208
__device__ uint32_t g_wt2h[128*9*8*32];           // conv weights half2
__device__ float g_amp[(size_t)CV_QX*BB*HWSZ*COUT]; // conv partials [q][b][p][o]
__device__ float g_feat[(size_t)BB*FEAT];         // tf32-rounded fp32
__device__ float g_p6[(size_t)FC6_KT*REP*BB];
__device__ float g_h6[BB*REP];

// ---------------- PTX helpers ----------------
__device__ __forceinline__ uint32_t smem_u32(const void* p) {
    uint32_t a;
    asm("{ .reg .u64 t; cvta.to.shared.u64 t, %1; cvt.u32.u64 %0, t; }" : "=r"(a) : "l"(p));
    return a;
}
__device__ __forceinline__ float rna_tf32(float x) {
    uint32_t u; asm("cvt.rna.tf32.f32 %0, %1;" : "=r"(u) : "f"(x));
    return __uint_as_float(u);
}
__device__ __forceinline__ uint32_t rna_u(uint32_t bits) {
    uint32_t u; asm("cvt.rna.tf32.f32 %0, %1;" : "=r"(u) : "f"(__uint_as_float(bits)));
    return u;
}
__device__ __forceinline__ uint32_t pack_h2(float a, float b) {
    __half2 h = __floats2half2_rn(a, b);
    return *(uint32_t*)&h;
}
__device__ __forceinline__ void cp_async16(uint32_t dst, const void* src) {
    asm volatile("cp.async.cg.shared.global [%0], [%1], 16;" :: "r"(dst), "l"(src) : "memory");
}
__device__ __forceinline__ void cp_commit() {
    asm volatile("cp.async.commit_group;" ::: "memory");
}
template <int N>
__device__ __forceinline__ void cp_wait() {
    asm volatile("cp.async.wait_group %0;" :: "n"(N) : "memory");
}
__device__ __forceinline__ void mma_tf32(float* c, const uint32_t* a, const uint32_t* b) {
    asm volatile(
        "mma.sync.aligned.m16n8k8.row.col.f32.tf32.tf32.f32 "
        "{%0,%1,%2,%3}, {%4,%5,%6,%7}, {%8,%9}, {%0,%1,%2,%3};"
        : "+f"(c[0]), "+f"(c[1]), "+f"(c[2]), "+f"(c[3])
        : "r"(a[0]), "r"(a[1]), "r"(a[2]), "r"(a[3]), "r"(b[0]), "r"(b[1]));
}
__device__ __forceinline__ void mma_f16(float* c, const uint32_t* a, const uint32_t* b) {
    asm volatile(
        "mma.sync.aligned.m16n8k16.row.col.f32.f16.f16.f32 "
        "{%0,%1,%2,%3}, {%4,%5,%6,%7}, {%8,%9}, {%0,%1,%2,%3};"
        : "+f"(c[0]), "+f"(c[1]), "+f"(c[2]), "+f"(c[3])
        : "r"(a[0]), "r"(a[1]), "r"(a[2]), "r"(a[3]), "r"(b[0]), "r"(b[1]));
}

// ============================================================
// Kernel 0: fused prepass (3 sections by blockIdx.x)
// ============================================================
__global__ void __launch_bounds__(256)
prep_kernel(const float* __restrict__ x, const float* __restrict__ w)
{
    const size_t blk = blockIdx.x;
    if (blk < NPA) {
        // conv x canvas: half2(ci even, ci odd) per 16x16 pos, border zero
        size_t idx = blk * 256 + threadIdx.x;
        int pos = (int)(idx & 255);
        size_t bp = idx >> 8;
        int pg = (int)(bp & 1023);
        int b  = (int)(bp >> 10);
        int r = pos >> 4, c = pos & 15;
        float v0 = 0.f, v1 = 0.f;
        if (r >= 1 && r <= 14 && c >= 1 && c <= 14) {
            const float* src = x + ((size_t)b * CIN + 2 * pg) * HWSZ + (r - 1) * WW + (c - 1);
            v0 = src[0];
            v1 = src[HWSZ];
        }
        g_xph[idx] = pack_h2(v0, v1);
    } else if (blk < NPA + NPB) {
        // einsum x: half2(pos even, pos odd), K padded to 208
        size_t idx = (blk - NPA) * 256 + threadIdx.x;
        int j = (int)(idx % 104);
        size_t bc = idx / 104;
        int p0 = 2 * j, p1 = 2 * j + 1;
        const float* src = x + bc * HWSZ;
        float v0 = (p0 < HWSZ) ? src[p0] : 0.f;
        float v1 = (p1 < HWSZ) ? src[p1] : 0.f;
        g_xe[idx] = pack_h2(v0, v1);
    } else {
        // conv weights half2: [chunk][tap][kpair][o]
        int idx = (int)(blk - NPA - NPB) * 256 + threadIdx.x;
        int o   = idx & 31;
        int kp  = (idx >> 5) & 7;
        int tap = (idx >> 8) % 9;
        int ch  = idx / (9 * 8 * 32);
        int ci0 = ch * 16 + 2 * kp;
        float v0 = w[(size_t)o * (CIN * 9) + (size_t)ci0 * 9 + tap];
        float v1 = w[(size_t)o * (CIN * 9) + (size_t)(ci0 + 1) * 9 + tap];
        g_wt2h[idx] = pack_h2(v0, v1);
    }
}

// ============================================================
// Kernel 1: conv via fp16 implicit GEMM. grid (8, 64) for wave balance.
// ============================================================
__constant__ int TAPD[9] = {0, 1, 2, 16, 17, 18, 32, 33, 34};

__global__ void __launch_bounds__(256)
conv_kernel()
{
    extern __shared__ uint32_t csm[];
    const uint32_t sb = smem_u32(csm);
    const int qx  = blockIdx.x;            // 0..7
    const int b   = blockIdx.y;
    const int tid = threadIdx.x;
    const int wz  = tid >> 5;
    const int lane = tid & 31;
    const int qm = lane >> 2, qk = lane & 3;

    int  ib[2][2];
    bool pv[2][2];
    #pragma unroll
    for (int t = 0; t < 2; t++) {
        #pragma unroll
        for (int h = 0; h < 2; h++) {
            int p = (wz * 2 + t) * 16 + qm + h * 8;
            bool v = p < HWSZ;
            int pr = v ? p / 14 : 0, pc = v ? p % 14 : 0;
            ib[t][h] = pr * 16 + pc;
            pv[t][h] = v;
        }
    }

    auto prefetch = [&](int ch, int pbuf) {
        const uint32_t xbuf = sb + (uint32_t)pbuf * (CV_STAGE_U32 * 4);
        const uint32_t wbuf = xbuf + CV_XS_U32 * 4;
        const int pg0 = qx * 128 + ch * 8;
        const int chg = qx * CV_NCH + ch;
        #pragma unroll
        for (int q = tid; q < 512; q += 256) {
            int kp = q >> 6, j = q & 63;
            cp_async16(xbuf + (uint32_t)(kp * CV_XSTR + j * 4) * 4,
                       g_xph + ((size_t)(b * 1024 + pg0 + kp)) * 256 + j * 4);
        }
        for (int q = tid; q < 576; q += 256) {
            int tap = q / 64;
            int kp  = (q >> 3) & 7;
            int oq  = q & 7;
            cp_async16(wbuf + (uint32_t)(tap * CV_WTAP + kp * CV_WSTR + oq * 4) * 4,
                       g_wt2h + ((size_t)(chg * 9 + tap) * 8 + kp) * 32 + oq * 4);
        }
    };

    float acc[2][4][4];
    #pragma unroll
    for (int t = 0; t < 2; t++)
        #pragma unroll
        for (int n = 0; n < 4; n++)
            #pragma unroll
            for (int i = 0; i < 4; i++) acc[t][n][i] = 0.f;

    prefetch(0, 0);
    cp_commit();

    #pragma unroll 1
    for (int ch = 0; ch < CV_NCH; ch++) {
        if (ch + 1 < CV_NCH) {
            prefetch(ch + 1, (ch + 1) & 1);
            cp_commit();
            cp_wait<1>();
        } else {
            cp_wait<0>();
        }
        __syncthreads();

        const uint32_t* Xs = csm + (ch & 1) * CV_STAGE_U32;
        const uint32_t* Ws = Xs + CV_XS_U32;

        #pragma unroll
        for (int tap = 0; tap < 9; tap++) {
            const int d = TAPD[tap];
            uint32_t a[2][4];
            #pragma unroll
            for (int t = 0; t < 2; t++) {
                a[t][0] = Xs[qk * CV_XSTR + ib[t][0] + d];
                a[t][1] = Xs[qk * CV_XSTR + ib[t][1] + d];
                a[t][2] = Xs[(qk + 4) * CV_XSTR + ib[t][0] + d];
                a[t][3] = Xs[(qk + 4) * CV_XSTR + ib[t][1] + d];
            }
            #pragma unroll
            for (int nt = 0; nt < 4; nt++) {
                uint32_t bf[2];
                bf[0] = Ws[tap * CV_WTAP + qk * CV_WSTR + nt * 8 + qm];
                bf[1] = Ws[tap * CV_WTAP + (qk + 4) * CV_WSTR + nt * 8 + qm];
                mma_f16(acc[0][nt], a[0], bf);
                mma_f16(acc[1][nt], a[1], bf);
            }
        }
        __syncthreads();
    }

    float* dst = g_amp + ((size_t)qx * BB + b) * (HWSZ * COUT);
    #pragma unroll
    for (int t = 0; t < 2; t++) {
        #pragma unroll
        for (int h = 0; h < 2; h++) {
            if (!pv[t][h]) continue;
            int p = (wz * 2 + t) * 16 + qm + h * 8;
            #pragma unroll
            for (int nt = 0; nt < 4; nt++) {
                *(float2*)(dst + p * COUT + nt * 8 + 2 * qk) =
                    make_float2(acc[t][nt][h * 2], acc[t][nt][h * 2 + 1]);
            }
        }
    }
}

// ============================================================
// Kernel 2: einsum (fp16 mma, K=208) with inline am partial-reduce.
// grid (8, 64): 256-cin tile x batch. block 256 (8 warps).
// smem rows (u32 stride EM_STRU): 0-31 am, 32-63 xbuf0, 64-95 xbuf1.
// ============================================================
__global__ void __launch_bounds__(256)
einsum_kernel(const float* __restrict__ bias)
{
    extern __shared__ uint32_t esm[];
    const uint32_t sb = smem_u32(esm);

    const int mt  = blockIdx.x;           // 0..7
    const int b   = blockIdx.y;
    const int tid = threadIdx.x;
    const int wz  = tid >> 5;
    const int lane = tid & 31;
    const int qm = lane >> 2, qk = lane & 3;
    const int mh = wz >> 2, nt = wz & 3;
    const int i0 = mt * 256;

    auto prefetch_x = [&](int ch) {
        const uint32_t xbuf = sb + (uint32_t)((32 + 32 * (ch & 1)) * EM_STRU) * 4;
        for (int q = tid; q < 832; q += 256) {
            int row = q / 26, j = q % 26;
            cp_async16(xbuf + (uint32_t)(row * EM_STRU + j * 4) * 4,
                       g_xe + (size_t)(b * CIN + i0 + ch * 32 + row) * 104 + j * 4);
        }
    };

    prefetch_x(0);
    cp_commit();

    // build am tile in smem: reduce 8 conv partials + bias, pack half2
    {
        const size_t QSTR = (size_t)BB * HWSZ * COUT;
        const size_t base = (size_t)b * (HWSZ * COUT);
        for (int e = tid; e < 32 * 104; e += 256) {
            int o = e & 31, j = e >> 5;
            float s0 = 0.f, s1 = 0.f;
            int p0 = 2 * j, p1 = p0 + 1;
            if (p0 < HWSZ) {
                s0 = bias[o];
                #pragma unroll
                for (int q = 0; q < CV_QX; q++) s0 += g_amp[q * QSTR + base + (size_t)p0 * COUT + o];
            }
            if (p1 < HWSZ) {
                s1 = bias[o];
                #pragma unroll
                for (int q = 0; q < CV_QX; q++) s1 += g_amp[q * QSTR + base + (size_t)p1 * COUT + o];
            }
            esm[o * EM_STRU + j] = pack_h2(s0, s1);
        }
    }

    const float inv = 1.f / (float)HWSZ;

    #pragma unroll 1
    for (int ch = 0; ch < 8; ch++) {
        if (ch + 1 < 8) {
            prefetch_x(ch + 1);
            cp_commit();
            cp_wait<1>();
        } else {
            cp_wait<0>();
        }
        __syncthreads();

        const int arow0 = (32 + 32 * (ch & 1) + mh * 16 + qm) * EM_STRU;
        const int brow0 = (nt * 8 + qm) * EM_STRU;

        float acc[4] = {0.f, 0.f, 0.f, 0.f};
        #pragma unroll
        for (int ks = 0; ks < 13; ks++) {
            const int k0 = ks * 8;
            uint32_t a[4], bf[2];
            a[0] = esm[arow0 + k0 + qk];
            a[1] = esm[arow0 + 8 * EM_STRU + k0 + qk];
            a[2] = esm[arow0 + k0 + 4 + qk];
            a[3] = esm[arow0 + 8 * EM_STRU + k0 + 4 + qk];
            bf[0] = esm[brow0 + k0 + qk];
            bf[1] = esm[brow0 + k0 + 4 + qk];
            mma_f16(acc, a, bf);
        }

        int i = i0 + ch * 32 + mh * 16 + qm;
        int o = nt * 8 + 2 * qk;
        float* d0 = g_feat + (size_t)b * FEAT + (size_t)i * COUT + o;
        *(float2*)d0 = make_float2(rna_tf32(acc[0] * inv), rna_tf32(acc[1] * inv));
        float* d1 = d0 + 8 * COUT;
        *(float2*)d1 = make_float2(rna_tf32(acc[2] * inv), rna_tf32(acc[3] * inv));
        __syncthreads();
    }
}

// ============================================================
// Kernel 3: fc6 partials, tf32 mma, 4-stage cp.async pipeline. (unchanged)
// grid (8, 32), block 256, 2 CTAs/SM. Chunk K=32, 64 chunks.
// ============================================================
__global__ void __launch_bounds__(256, 2)
fc6_kernel(const float* __restrict__ w6)
{
    extern __shared__ float fsm[];
    const uint32_t sb = smem_u32(fsm);

    const int mt  = blockIdx.x;
    const int kt  = blockIdx.y;
    const int tid = threadIdx.x;
    const int wz  = tid >> 5;
    const int lane = tid & 31;
    const int qm = lane >> 2, qk = lane & 3;

    const int    mbase = mt * 128;
    const size_t kbase = (size_t)kt * FC6_KPER;

    const int arow = tid >> 1, akoff = (tid & 1) * 16;
    const int brow = tid >> 2, bkoff = (tid & 3) * 8;
    const float* ga0 = w6 + (size_t)(mbase + arow) * FEAT + kbase + akoff;
    const float* gb0 = g_feat + (size_t)brow * FEAT + kbase + bkoff;

    auto prefetch = [&](int ch) {
        const int st = ch & 3;
        const uint32_t abuf = sb + (uint32_t)st * (STAGE_FLOATS * 4);
        const uint32_t bbuf = abuf + A_FLOATS * 4;
        const float* ga = ga0 + (size_t)ch * FC6_KC;
        const uint32_t adst = abuf + (uint32_t)(arow * F6_STR + akoff) * 4;
        #pragma unroll
        for (int j = 0; j < 4; j++)
            cp_async16(adst + j * 16, ga + j * 4);
        const float* gb = gb0 + (size_t)ch * FC6_KC;
        const uint32_t bdst = bbuf + (uint32_t)(brow * F6_STR + bkoff) * 4;
        #pragma unroll
        for (int j = 0; j < 2; j++)
            cp_async16(bdst + j * 16, gb + j * 4);
    };

    float acc[8][4];
    #pragma unroll
    for (int j = 0; j < 8; j++)
        #pragma unroll
        for (int r = 0; r < 4; r++) acc[j][r] = 0.f;

    prefetch(0); cp_commit();
    prefetch(1); cp_commit();
    prefetch(2); cp_commit();

    #pragma unroll 1
    for (int ch = 0; ch < FC6_NCHUNK; ch++) {
        if (ch + 3 < FC6_NCHUNK) {
            prefetch(ch + 3);
            cp_commit();
            cp_wait<3>();
        } else if (ch + 2 < FC6_NCHUNK) {
            cp_wait<2>();
        } else if (ch + 1 < FC6_NCHUNK) {
            cp_wait<1>();
        } else {
            cp_wait<0>();
        }
        __syncthreads();

        const float* As = fsm + (ch & 3) * STAGE_FLOATS;
        const uint32_t* Au = (const uint32_t*)As;
        const uint32_t* Bu = Au + A_FLOATS;
        const int m0 = wz * 16;

        #pragma unroll
        for (int ks = 0; ks < 4; ks++) {
            const int k0 = ks * 8;
            uint32_t a[4];
            a[0] = rna_u(Au[(m0 + qm) * F6_STR + k0 + qk]);
            a[1] = rna_u(Au[(m0 + qm + 8) * F6_STR + k0 + qk]);
            a[2] = rna_u(Au[(m0 + qm) * F6_STR + k0 + 4 + qk]);
            a[3] = rna_u(Au[(m0 + qm + 8) * F6_STR + k0 + 4 + qk]);
            #pragma unroll
            for (int nt = 0; nt < 8; nt++) {
                uint32_t bf[2];
                bf[0] = Bu[(nt * 8 + qm) * F6_STR + k0 + qk];
                bf[1] = Bu[(nt * 8 + qm) * F6_STR + k0 + 4 + qk];
                mma_tf32(acc[nt], a, bf);
            }
        }
        __syncthreads();
    }

    const int r = mbase + wz * 16 + qm;
    #pragma unroll
    for (int nt = 0; nt < 8; nt++) {
        int bcol = nt * 8 + 2 * qk;
        *(float2*)(g_p6 + ((size_t)kt * REP + r) * BB + bcol) =
            make_float2(acc[nt][0], acc[nt][1]);
        *(float2*)(g_p6 + ((size_t)kt * REP + r + 8) * BB + bcol) =
            make_float2(acc[nt][2], acc[nt][3]);
    }
}

// ============================================================
// Kernel 4: reduce fc6 partials + bias + relu -> g_h6
// ============================================================
__global__ void __launch_bounds__(256)
reduce6_kernel(const float* __restrict__ b6)
{
    int idx = blockIdx.x * 256 + threadIdx.x;
    int r = idx >> 6, b = idx & 63;
    float sum = b6[r];
    #pragma unroll 8
    for (int kt = 0; kt < FC6_KT; kt++)
        sum += g_p6[((size_t)kt * REP + r) * BB + b];
    g_h6[(size_t)b * REP + r] = fmaxf(sum, 0.f);
}

// ============================================================
// Kernel 5: fc7 + bias + relu. grid (16 bgroups, 4 r-quarters).
// ============================================================
__global__ void __launch_bounds__(256)
fc7_kernel(const float* __restrict__ w7, const float* __restrict__ b7,
           float* __restrict__ out)
{
    const int b0 = blockIdx.x * 4;
    const int r  = blockIdx.y * 256 + threadIdx.x;
    const int tid = threadIdx.x;

    __shared__ float hs[4][REP];
    for (int t = tid; t < 4 * REP; t += 256)
        hs[t >> 10][t & 1023] = g_h6[(size_t)(b0 + (t >> 10)) * REP + (t & 1023)];
    __syncthreads();

    const float4* wr = (const float4*)(w7 + (size_t)r * REP);
    float s0 = 0.f, s1 = 0.f, s2 = 0.f, s3 = 0.f;
    #pragma unroll 4
    for (int k4 = 0; k4 < REP / 4; k4++) {
        float4 wv = wr[k4];
        float4 h0 = *(const float4*)&hs[0][k4 * 4];
        float4 h1 = *(const float4*)&hs[1][k4 * 4];
        float4 h2 = *(const float4*)&hs[2][k4 * 4];
        float4 h3 = *(const float4*)&hs[3][k4 * 4];
        s0 += wv.x * h0.x + wv.y * h0.y + wv.z * h0.z + wv.w * h0.w;
        s1 += wv.x * h1.x + wv.y * h1.y + wv.z * h1.z + wv.w * h1.w;
        s2 += wv.x * h2.x + wv.y * h2.y + wv.z * h2.z + wv.w * h2.w;
        s3 += wv.x * h3.x + wv.y * h3.y + wv.z * h3.z + wv.w * h3.w;
    }
    float bv = b7[r];
    out[(size_t)(b0 + 0) * REP + r] = fmaxf(s0 + bv, 0.f);
    out[(size_t)(b0 + 1) * REP + r] = fmaxf(s1 + bv, 0.f);
    out[(size_t)(b0 + 2) * REP + r] = fmaxf(s2 + bv, 0.f);
    out[(size_t)(b0 + 3) * REP + r] = fmaxf(s3 + bv, 0.f);
}

// ============================================================
// launch (fc6 is 4th launch -> profiled)
// ============================================================
extern "C" void kernel_launch(void* const* d_in, const int* in_sizes, int n_in,
                              void* d_out, int out_size)
{
    const float* x      = (const float*)d_in[0];
    const float* conv_w = (const float*)d_in[1];
    const float* conv_b = (const float*)d_in[2];
    const float* w6     = (const float*)d_in[3];
    const float* b6     = (const float*)d_in[4];
    const float* w7     = (const float*)d_in[5];
    const float* b7     = (const float*)d_in[6];
    float* out = (float*)d_out;

    cudaFuncSetAttribute(conv_kernel,   cudaFuncAttributeMaxDynamicSharedMemorySize, CONV_SMEM);
    cudaFuncSetAttribute(einsum_kernel, cudaFuncAttributeMaxDynamicSharedMemorySize, EM_SMEM);
    cudaFuncSetAttribute(fc6_kernel,    cudaFuncAttributeMaxDynamicSharedMemorySize, FC6_SMEM);

    unsigned nprep = (unsigned)(NPA + NPB + NPC);
    prep_kernel   <<<dim3(nprep), 256>>>(x, conv_w);
    conv_kernel   <<<dim3(CV_QX, BB), 256, CONV_SMEM>>>();
    einsum_kernel <<<dim3(8, BB), 256, EM_SMEM>>>(conv_b);
    fc6_kernel    <<<dim3(8, FC6_KT), 256, FC6_SMEM>>>(w6);
    reduce6_kernel<<<dim3(BB * REP / 256), 256>>>(b6);
    fc7_kernel    <<<dim3(16, 4), 256>>>(w7, b7, out);
}

// round 10
// speedup vs baseline: 1.0854x; 1.0854x over previous
#include <cuda_runtime.h>
#include <cuda_fp16.h>
#include <cstdint>

// ---------------- problem constants ----------------
#define BB    64
#define CIN   2048
#define COUT  32
#define HH    14
#define WW    14
#define HWSZ  196
#define REP   1024
#define FEAT  (CIN*COUT)   // 65536

// ---------------- conv tiling (fp16) ----------------
#define CV_QX      8
#define CV_NCH     16
#define CV_XSTR    264
#define CV_WSTR    40
#define CV_WTAP    (8*CV_WSTR)
#define CV_XS_U32  (8*CV_XSTR)
#define CV_WS_U32  (9*CV_WTAP)
#define CV_STAGE_U32 (CV_XS_U32+CV_WS_U32)
#define CONV_SMEM  (2*CV_STAGE_U32*4)      // 39936 B

// ---------------- einsum tiling (fp16, K=208) ----------------
#define EM_STRU    108
#define EM_SMEM    (96*EM_STRU*4)          // 41472 B

// ---------------- fc6 tiling (fp16 mma, 4-stage pipeline) ----------------
#define FC6_KT     32
#define FC6_KPER   (FEAT/FC6_KT)           // 2048
#define FC6_KC     32                      // K values per chunk
#define FC6_NCHUNK (FC6_KPER/FC6_KC)       // 64
#define F6_ASTR    40                      // A row stride in floats (32 data + 8 pad)
#define F6_BSTR    20                      // B row stride in u32 (16 data + 4 pad)
#define A_U32      (128*F6_ASTR)           // 5120
#define B_U32      (64*F6_BSTR)            // 1280
#define STAGE_U32  (A_U32+B_U32)           // 6400
#define FC6_NSTG   4
#define FC6_SMEM   (FC6_NSTG*STAGE_U32*4)  // 102400 B

// ---------------- prep sections ----------------
#define NPA  ((size_t)BB*1024*256/256)
#define NPB  ((size_t)BB*CIN*104/256)
#define NPC  (128*9*8*32/256)

// ---------------- scratch (device globals) ----------------
__device__ uint32_t g_xph[(size_t)BB*1024*256];     // conv x canvas half2
__device__ uint32_t g_xe[(size_t)BB*CIN*104];       // einsum x half2, K=208
__device__ uint32_t g_wt2h[128*9*8*32];             // conv weights half2
__device__ float g_amp[(size_t)CV_QX*BB*HWSZ*COUT]; // conv partials [q][b][p][o]
__device__ uint32_t g_feath[(size_t)BB*FEAT/2];     // feat as half2 (k-pairs)
__device__ float g_p6[(size_t)FC6_KT*REP*BB];
__device__ float g_h6[BB*REP];

// ---------------- PTX helpers ----------------
__device__ __forceinline__ uint32_t smem_u32(const void* p) {
    uint32_t a;
    asm("{ .reg .u64 t; cvta.to.shared.u64 t, %1; cvt.u32.u64 %0, t; }" : "=r"(a) : "l"(p));
    return a;
}
__device__ __forceinline__ uint32_t pack_h2(float a, float b) {
    __half2 h = __floats2half2_rn(a, b);
    return *(uint32_t*)&h;
}
__device__ __forceinline__ void cp_async16(uint32_t dst, const void* src) {
    asm volatile("cp.async.cg.shared.global [%0], [%1], 16;" :: "r"(dst), "l"(src) : "memory");
}
__device__ __forceinline__ void cp_commit() {
    asm volatile("cp.async.commit_group;" ::: "memory");
}
template <int N>
__device__ __forceinline__ void cp_wait() {
    asm volatile("cp.async.wait_group %0;" :: "n"(N) : "memory");
}
__device__ __forceinline__ void mma_f16(float* c, const uint32_t* a, const uint32_t* b) {
    asm volatile(
        "mma.sync.aligned.m16n8k16.row.col.f32.f16.f16.f32 "
        "{%0,%1,%2,%3}, {%4,%5,%6,%7}, {%8,%9}, {%0,%1,%2,%3};"
        : "+f"(c[0]), "+f"(c[1]), "+f"(c[2]), "+f"(c[3])
        : "r"(a[0]), "r"(a[1]), "r"(a[2]), "r"(a[3]), "r"(b[0]), "r"(b[1]));
}

// ============================================================
// Kernel 0: fused prepass (3 sections by blockIdx.x)
// ============================================================
__global__ void __launch_bounds__(256)
prep_kernel(const float* __restrict__ x, const float* __restrict__ w)
{
    const size_t blk = blockIdx.x;
    if (blk < NPA) {
        size_t idx = blk * 256 + threadIdx.x;
        int pos = (int)(idx & 255);
        size_t bp = idx >> 8;
        int pg = (int)(bp & 1023);
        int b  = (int)(bp >> 10);
        int r = pos >> 4, c = pos & 15;
        float v0 = 0.f, v1 = 0.f;
        if (r >= 1 && r <= 14 && c >= 1 && c <= 14) {
            const float* src = x + ((size_t)b * CIN + 2 * pg) * HWSZ + (r - 1) * WW + (c - 1);
            v0 = src[0];
            v1 = src[HWSZ];
        }
        g_xph[idx] = pack_h2(v0, v1);
    } else if (blk < NPA + NPB) {
        size_t idx = (blk - NPA) * 256 + threadIdx.x;
        int j = (int)(idx % 104);
        size_t bc = idx / 104;
        int p0 = 2 * j, p1 = 2 * j + 1;
        const float* src = x + bc * HWSZ;
        float v0 = (p0 < HWSZ) ? src[p0] : 0.f;
        float v1 = (p1 < HWSZ) ? src[p1] : 0.f;
        g_xe[idx] = pack_h2(v0, v1);
    } else {
        int idx = (int)(blk - NPA - NPB) * 256 + threadIdx.x;
        int o   = idx & 31;
        int kp  = (idx >> 5) & 7;
        int tap = (idx >> 8) % 9;
        int ch  = idx / (9 * 8 * 32);
        int ci0 = ch * 16 + 2 * kp;
        float v0 = w[(size_t)o * (CIN * 9) + (size_t)ci0 * 9 + tap];
        float v1 = w[(size_t)o * (CIN * 9) + (size_t)(ci0 + 1) * 9 + tap];
        g_wt2h[idx] = pack_h2(v0, v1);
    }
}

// ============================================================
// Kernel 1: conv via fp16 implicit GEMM. grid (8, 64). (unchanged)
// ============================================================
__constant__ int TAPD[9] = {0, 1, 2, 16, 17, 18, 32, 33, 34};

__global__ void __launch_bounds__(256)
conv_kernel()
{
    extern __shared__ uint32_t csm[];
    const uint32_t sb = smem_u32(csm);
    const int qx  = blockIdx.x;
    const int b   = blockIdx.y;
    const int tid = threadIdx.x;
    const int wz  = tid >> 5;
    const int lane = tid & 31;
    const int qm = lane >> 2, qk = lane & 3;

    int  ib[2][2];
    bool pv[2][2];
    #pragma unroll
    for (int t = 0; t < 2; t++) {
        #pragma unroll
        for (int h = 0; h < 2; h++) {
            int p = (wz * 2 + t) * 16 + qm + h * 8;
            bool v = p < HWSZ;
            int pr = v ? p / 14 : 0, pc = v ? p % 14 : 0;
            ib[t][h] = pr * 16 + pc;
            pv[t][h] = v;
        }
    }

    auto prefetch = [&](int ch, int pbuf) {
        const uint32_t xbuf = sb + (uint32_t)pbuf * (CV_STAGE_U32 * 4);
        const uint32_t wbuf = xbuf + CV_XS_U32 * 4;
        const int pg0 = qx * 128 + ch * 8;
        const int chg = qx * CV_NCH + ch;
        #pragma unroll
        for (int q = tid; q < 512; q += 256) {
            int kp = q >> 6, j = q & 63;
            cp_async16(xbuf + (uint32_t)(kp * CV_XSTR + j * 4) * 4,
                       g_xph + ((size_t)(b * 1024 + pg0 + kp)) * 256 + j * 4);
        }
        for (int q = tid; q < 576; q += 256) {
            int tap = q / 64;
            int kp  = (q >> 3) & 7;
            int oq  = q & 7;
            cp_async16(wbuf + (uint32_t)(tap * CV_WTAP + kp * CV_WSTR + oq * 4) * 4,
                       g_wt2h + ((size_t)(chg * 9 + tap) * 8 + kp) * 32 + oq * 4);
        }
    };

    float acc[2][4][4];
    #pragma unroll
    for (int t = 0; t < 2; t++)
        #pragma unroll
        for (int n = 0; n < 4; n++)
            #pragma unroll
            for (int i = 0; i < 4; i++) acc[t][n][i] = 0.f;

    prefetch(0, 0);
    cp_commit();

    #pragma unroll 1
    for (int ch = 0; ch < CV_NCH; ch++) {
        if (ch + 1 < CV_NCH) {
            prefetch(ch + 1, (ch + 1) & 1);
            cp_commit();
            cp_wait<1>();
        } else {
            cp_wait<0>();
        }
        __syncthreads();

        const uint32_t* Xs = csm + (ch & 1) * CV_STAGE_U32;
        const uint32_t* Ws = Xs + CV_XS_U32;

        #pragma unroll
        for (int tap = 0; tap < 9; tap++) {
            const int d = TAPD[tap];
            uint32_t a[2][4];
            #pragma unroll
            for (int t = 0; t < 2; t++) {
                a[t][0] = Xs[qk * CV_XSTR + ib[t][0] + d];
                a[t][1] = Xs[qk * CV_XSTR + ib[t][1] + d];
                a[t][2] = Xs[(qk + 4) * CV_XSTR + ib[t][0] + d];
                a[t][3] = Xs[(qk + 4) * CV_XSTR + ib[t][1] + d];
            }
            #pragma unroll
            for (int nt = 0; nt < 4; nt++) {
                uint32_t bf[2];
                bf[0] = Ws[tap * CV_WTAP + qk * CV_WSTR + nt * 8 + qm];
                bf[1] = Ws[tap * CV_WTAP + (qk + 4) * CV_WSTR + nt * 8 + qm];
                mma_f16(acc[0][nt], a[0], bf);
                mma_f16(acc[1][nt], a[1], bf);
            }
        }
        __syncthreads();
    }

    float* dst = g_amp + ((size_t)qx * BB + b) * (HWSZ * COUT);
    #pragma unroll
    for (int t = 0; t < 2; t++) {
        #pragma unroll
        for (int h = 0; h < 2; h++) {
            if (!pv[t][h]) continue;
            int p = (wz * 2 + t) * 16 + qm + h * 8;
            #pragma unroll
            for (int nt = 0; nt < 4; nt++) {
                *(float2*)(dst + p * COUT + nt * 8 + 2 * qk) =
                    make_float2(acc[t][nt][h * 2], acc[t][nt][h * 2 + 1]);
            }
        }
    }
}

// ============================================================
// Kernel 2: einsum (fp16 mma, K=208) with inline am partial-reduce.
// Output now packed half2 into g_feath.
// ============================================================
__global__ void __launch_bounds__(256)
einsum_kernel(const float* __restrict__ bias)
{
    extern __shared__ uint32_t esm[];
    const uint32_t sb = smem_u32(esm);

    const int mt  = blockIdx.x;           // 0..7
    const int b   = blockIdx.y;
    const int tid = threadIdx.x;
    const int wz  = tid >> 5;
    const int lane = tid & 31;
    const int qm = lane >> 2, qk = lane & 3;
    const int mh = wz >> 2, nt = wz & 3;
    const int i0 = mt * 256;

    auto prefetch_x = [&](int ch) {
        const uint32_t xbuf = sb + (uint32_t)((32 + 32 * (ch & 1)) * EM_STRU) * 4;
        for (int q = tid; q < 832; q += 256) {
            int row = q / 26, j = q % 26;
            cp_async16(xbuf + (uint32_t)(row * EM_STRU + j * 4) * 4,
                       g_xe + (size_t)(b * CIN + i0 + ch * 32 + row) * 104 + j * 4);
        }
    };

    prefetch_x(0);
    cp_commit();

    // build am tile in smem: reduce 8 conv partials + bias, pack half2
    {
        const size_t QSTR = (size_t)BB * HWSZ * COUT;
        const size_t base = (size_t)b * (HWSZ * COUT);
        for (int e = tid; e < 32 * 104; e += 256) {
            int o = e & 31, j = e >> 5;
            float s0 = 0.f, s1 = 0.f;
            int p0 = 2 * j, p1 = p0 + 1;
            if (p0 < HWSZ) {
                s0 = bias[o];
                #pragma unroll
                for (int q = 0; q < CV_QX; q++) s0 += g_amp[q * QSTR + base + (size_t)p0 * COUT + o];
            }
            if (p1 < HWSZ) {
                s1 = bias[o];
                #pragma unroll
                for (int q = 0; q < CV_QX; q++) s1 += g_amp[q * QSTR + base + (size_t)p1 * COUT + o];
            }
            esm[o * EM_STRU + j] = pack_h2(s0, s1);
        }
    }

    const float inv = 1.f / (float)HWSZ;

    #pragma unroll 1
    for (int ch = 0; ch < 8; ch++) {
        if (ch + 1 < 8) {
            prefetch_x(ch + 1);
            cp_commit();
            cp_wait<1>();
        } else {
            cp_wait<0>();
        }
        __syncthreads();

        const int arow0 = (32 + 32 * (ch & 1) + mh * 16 + qm) * EM_STRU;
        const int brow0 = (nt * 8 + qm) * EM_STRU;

        float acc[4] = {0.f, 0.f, 0.f, 0.f};
        #pragma unroll
        for (int ks = 0; ks < 13; ks++) {
            const int k0 = ks * 8;
            uint32_t a[4], bf[2];
            a[0] = esm[arow0 + k0 + qk];
            a[1] = esm[arow0 + 8 * EM_STRU + k0 + qk];
            a[2] = esm[arow0 + k0 + 4 + qk];
            a[3] = esm[arow0 + 8 * EM_STRU + k0 + 4 + qk];
            bf[0] = esm[brow0 + k0 + qk];
            bf[1] = esm[brow0 + k0 + 4 + qk];
            mma_f16(acc, a, bf);
        }

        int i = i0 + ch * 32 + mh * 16 + qm;
        int o = nt * 8 + 2 * qk;                 // even
        size_t k0h = ((size_t)b * FEAT + (size_t)i * COUT + o) >> 1;
        g_feath[k0h] = pack_h2(acc[0] * inv, acc[1] * inv);
        size_t k1h = ((size_t)b * FEAT + (size_t)(i + 8) * COUT + o) >> 1;
        g_feath[k1h] = pack_h2(acc[2] * inv, acc[3] * inv);
        __syncthreads();
    }
}

// ============================================================
// Kernel 3: fc6 partials, fp16 mma (m16n8k16), 4-stage cp.async pipeline.
// grid (8, 32), block 256, 2 CTAs/SM. A = w6 fp32 (cvt in-reg), B = feat half2.
// ============================================================
__global__ void __launch_bounds__(256, 2)
fc6_kernel(const float* __restrict__ w6)
{
    extern __shared__ uint32_t fsm[];
    const uint32_t sb = smem_u32(fsm);

    const int mt  = blockIdx.x;
    const int kt  = blockIdx.y;
    const int tid = threadIdx.x;
    const int wz  = tid >> 5;
    const int lane = tid & 31;
    const int qm = lane >> 2, qk = lane & 3;

    const int    mbase = mt * 128;
    const size_t kbase = (size_t)kt * FC6_KPER;

    const int arow = tid >> 1, akoff = (tid & 1) * 16;   // floats
    const int brow = tid >> 2, bu = (tid & 3) * 4;       // u32
    const float*    ga0 = w6 + (size_t)(mbase + arow) * FEAT + kbase + akoff;
    const uint32_t* gb0 = g_feath + ((size_t)brow * FEAT + kbase) / 2 + bu;

    auto prefetch = [&](int ch) {
        const int st = ch & 3;
        const uint32_t abuf = sb + (uint32_t)st * (STAGE_U32 * 4);
        const uint32_t bbuf = abuf + A_U32 * 4;
        const float* ga = ga0 + (size_t)ch * FC6_KC;
        const uint32_t adst = abuf + (uint32_t)(arow * F6_ASTR + akoff) * 4;
        #pragma unroll
        for (int j = 0; j < 4; j++)
            cp_async16(adst + j * 16, ga + j * 4);
        const uint32_t* gb = gb0 + (size_t)ch * (FC6_KC / 2);
        cp_async16(bbuf + (uint32_t)(brow * F6_BSTR + bu) * 4, gb);
    };

    float acc[8][4];
    #pragma unroll
    for (int j = 0; j < 8; j++)
        #pragma unroll
        for (int r = 0; r < 4; r++) acc[j][r] = 0.f;

    prefetch(0); cp_commit();
    prefetch(1); cp_commit();
    prefetch(2); cp_commit();

    #pragma unroll 1
    for (int ch = 0; ch < FC6_NCHUNK; ch++) {
        if (ch + 3 < FC6_NCHUNK) {
            prefetch(ch + 3);
            cp_commit();
            cp_wait<3>();
        } else if (ch + 2 < FC6_NCHUNK) {
            cp_wait<2>();
        } else if (ch + 1 < FC6_NCHUNK) {
            cp_wait<1>();
        } else {
            cp_wait<0>();
        }
        __syncthreads();

        const float*    As = (const float*)(fsm + (ch & 3) * STAGE_U32);
        const uint32_t* Bs = fsm + (ch & 3) * STAGE_U32 + A_U32;
        const int m0 = wz * 16;

        #pragma unroll
        for (int s = 0; s < 2; s++) {
            const int kb = s * 16;               // float offset within A row
            uint32_t a[4];
            {
                float2 v0 = *(const float2*)(As + (m0 + qm) * F6_ASTR + kb + 2 * qk);
                float2 v1 = *(const float2*)(As + (m0 + qm + 8) * F6_ASTR + kb + 2 * qk);
                float2 v2 = *(const float2*)(As + (m0 + qm) * F6_ASTR + kb + 8 + 2 * qk);
                float2 v3 = *(const float2*)(As + (m0 + qm + 8) * F6_ASTR + kb + 8 + 2 * qk);
                a[0] = pack_h2(v0.x, v0.y);
                a[1] = pack_h2(v1.x, v1.y);
                a[2] = pack_h2(v2.x, v2.y);
                a[3] = pack_h2(v3.x, v3.y);
            }
            #pragma unroll
            for (int nt = 0; nt < 8; nt++) {
                uint32_t bf[2];
                bf[0] = Bs[(nt * 8 + qm) * F6_BSTR + s * 8 + qk];
                bf[1] = Bs[(nt * 8 + qm) * F6_BSTR + s * 8 + qk + 4];
                mma_f16(acc[nt], a, bf);
            }
        }
        __syncthreads();
    }

    const int r = mbase + wz * 16 + qm;
    #pragma unroll
    for (int nt = 0; nt < 8; nt++) {
        int bcol = nt * 8 + 2 * qk;
        *(float2*)(g_p6 + ((size_t)kt * REP + r) * BB + bcol) =
            make_float2(acc[nt][0], acc[nt][1]);
        *(float2*)(g_p6 + ((size_t)kt * REP + r + 8) * BB + bcol) =
            make_float2(acc[nt][2], acc[nt][3]);
    }
}

// ============================================================
// Kernel 4: reduce fc6 partials + bias + relu -> g_h6
// ============================================================
__global__ void __launch_bounds__(256)
reduce6_kernel(const float* __restrict__ b6)
{
    int idx = blockIdx.x * 256 + threadIdx.x;
    int r = idx >> 6, b = idx & 63;
    float sum = b6[r];
    #pragma unroll 8
    for (int kt = 0; kt < FC6_KT; kt++)
        sum += g_p6[((size_t)kt * REP + r) * BB + b];
    g_h6[(size_t)b * REP + r] = fmaxf(sum, 0.f);
}

// ============================================================
// Kernel 5: fc7 + bias + relu. grid (16 bgroups, 4 r-quarters).
// ============================================================
__global__ void __launch_bounds__(256)
fc7_kernel(const float* __restrict__ w7, const float* __restrict__ b7,
           float* __restrict__ out)
{
    const int b0 = blockIdx.x * 4;
    const int r  = blockIdx.y * 256 + threadIdx.x;
    const int tid = threadIdx.x;

    __shared__ float hs[4][REP];
    for (int t = tid; t < 4 * REP; t += 256)
        hs[t >> 10][t & 1023] = g_h6[(size_t)(b0 + (t >> 10)) * REP + (t & 1023)];
    __syncthreads();

    const float4* wr = (const float4*)(w7 + (size_t)r * REP);
    float s0 = 0.f, s1 = 0.f, s2 = 0.f, s3 = 0.f;
    #pragma unroll 4
    for (int k4 = 0; k4 < REP / 4; k4++) {
        float4 wv = wr[k4];
        float4 h0 = *(const float4*)&hs[0][k4 * 4];
        float4 h1 = *(const float4*)&hs[1][k4 * 4];
        float4 h2 = *(const float4*)&hs[2][k4 * 4];
        float4 h3 = *(const float4*)&hs[3][k4 * 4];
        s0 += wv.x * h0.x + wv.y * h0.y + wv.z * h0.z + wv.w * h0.w;
        s1 += wv.x * h1.x + wv.y * h1.y + wv.z * h1.z + wv.w * h1.w;
        s2 += wv.x * h2.x + wv.y * h2.y + wv.z * h2.z + wv.w * h2.w;
        s3 += wv.x * h3.x + wv.y * h3.y + wv.z * h3.z + wv.w * h3.w;
    }
    float bv = b7[r];
    out[(size_t)(b0 + 0) * REP + r] = fmaxf(s0 + bv, 0.f);
    out[(size_t)(b0 + 1) * REP + r] = fmaxf(s1 + bv, 0.f);
    out[(size_t)(b0 + 2) * REP + r] = fmaxf(s2 + bv, 0.f);
    out[(size_t)(b0 + 3) * REP + r] = fmaxf(s3 + bv, 0.f);
}

// ============================================================
// launch (fc6 is 4th launch -> profiled)
// ============================================================
extern "C" void kernel_launch(void* const* d_in, const int* in_sizes, int n_in,
                              void* d_out, int out_size)
{
    const float* x      = (const float*)d_in[0];
    const float* conv_w = (const float*)d_in[1];
    const float* conv_b = (const float*)d_in[2];
    const float* w6     = (const float*)d_in[3];
    const float* b6     = (const float*)d_in[4];
    const float* w7     = (const float*)d_in[5];
    const float* b7     = (const float*)d_in[6];
    float* out = (float*)d_out;

    cudaFuncSetAttribute(conv_kernel,   cudaFuncAttributeMaxDynamicSharedMemorySize, CONV_SMEM);
    cudaFuncSetAttribute(einsum_kernel, cudaFuncAttributeMaxDynamicSharedMemorySize, EM_SMEM);
    cudaFuncSetAttribute(fc6_kernel,    cudaFuncAttributeMaxDynamicSharedMemorySize, FC6_SMEM);

    unsigned nprep = (unsigned)(NPA + NPB + NPC);
    prep_kernel   <<<dim3(nprep), 256>>>(x, conv_w);
    conv_kernel   <<<dim3(CV_QX, BB), 256, CONV_SMEM>>>();
    einsum_kernel <<<dim3(8, BB), 256, EM_SMEM>>>(conv_b);
    fc6_kernel    <<<dim3(8, FC6_KT), 256, FC6_SMEM>>>(w6);
    reduce6_kernel<<<dim3(BB * REP / 256), 256>>>(b6);
    fc7_kernel    <<<dim3(16, 4), 256>>>(w7, b7, out);
}

// round 11
// speedup vs baseline: 1.1250x; 1.0365x over previous
#include <cuda_runtime.h>
#include <cuda_fp16.h>
#include <cstdint>

// ---------------- problem constants ----------------
#define BB    64
#define CIN   2048
#define COUT  32
#define HH    14
#define WW    14
#define HWSZ  196
#define REP   1024
#define FEAT  (CIN*COUT)   // 65536

// ---------------- conv tiling (fp16) ----------------
#define CV_QX      8
#define CV_NCH     16
#define CV_XSTR    264
#define CV_WSTR    40
#define CV_WTAP    (8*CV_WSTR)
#define CV_XS_U32  (8*CV_XSTR)
#define CV_WS_U32  (9*CV_WTAP)
#define CV_STAGE_U32 (CV_XS_U32+CV_WS_U32)
#define CONV_SMEM  (2*CV_STAGE_U32*4)      // 39936 B

// ---------------- einsum tiling (fp16, K=208) ----------------
#define EM_STRU    108
#define EM_SMEM    (96*EM_STRU*4)          // 41472 B

// ---------------- fc6 tiling (fp16 mma, M=64, 3 CTAs/SM) ----------------
#define FC6_MT     16                      // m tiles (64 rows each)
#define FC6_KT     32
#define FC6_KPER   (FEAT/FC6_KT)           // 2048
#define FC6_KC     32                      // K values per chunk
#define FC6_NCHUNK (FC6_KPER/FC6_KC)       // 64
#define F6_ASTR    40                      // A row stride in floats
#define F6_BSTR    20                      // B row stride in u32
#define A_U32      (64*F6_ASTR)            // 2560
#define B_U32      (64*F6_BSTR)            // 1280
#define STAGE_U32  (A_U32+B_U32)           // 3840
#define FC6_NSTG   4
#define FC6_SMEM   (FC6_NSTG*STAGE_U32*4)  // 61440 B -> 3 CTAs/SM

// ---------------- prep sections ----------------
#define NPA  ((size_t)BB*1024*256/256)
#define NPB  ((size_t)BB*CIN*104/256)
#define NPC  (128*9*8*32/256)

// ---------------- scratch (device globals) ----------------
__device__ uint32_t g_xph[(size_t)BB*1024*256];     // conv x canvas half2
__device__ uint32_t g_xe[(size_t)BB*CIN*104];       // einsum x half2, K=208
__device__ uint32_t g_wt2h[128*9*8*32];             // conv weights half2
__device__ float g_amp[(size_t)CV_QX*BB*HWSZ*COUT]; // conv partials [q][b][p][o]
__device__ uint32_t g_feath[(size_t)BB*FEAT/2];     // feat as half2 (k-pairs)
__device__ float g_p6[(size_t)FC6_KT*REP*BB];
__device__ float g_h6[BB*REP];

// ---------------- PTX helpers ----------------
__device__ __forceinline__ uint32_t smem_u32(const void* p) {
    uint32_t a;
    asm("{ .reg .u64 t; cvta.to.shared.u64 t, %1; cvt.u32.u64 %0, t; }" : "=r"(a) : "l"(p));
    return a;
}
__device__ __forceinline__ uint32_t pack_h2(float a, float b) {
    __half2 h = __floats2half2_rn(a, b);
    return *(uint32_t*)&h;
}
__device__ __forceinline__ void cp_async16(uint32_t dst, const void* src) {
    asm volatile("cp.async.cg.shared.global [%0], [%1], 16;" :: "r"(dst), "l"(src) : "memory");
}
__device__ __forceinline__ void cp_commit() {
    asm volatile("cp.async.commit_group;" ::: "memory");
}
template <int N>
__device__ __forceinline__ void cp_wait() {
    asm volatile("cp.async.wait_group %0;" :: "n"(N) : "memory");
}
__device__ __forceinline__ void mma_f16(float* c, const uint32_t* a, const uint32_t* b) {
    asm volatile(
        "mma.sync.aligned.m16n8k16.row.col.f32.f16.f16.f32 "
        "{%0,%1,%2,%3}, {%4,%5,%6,%7}, {%8,%9}, {%0,%1,%2,%3};"
        : "+f"(c[0]), "+f"(c[1]), "+f"(c[2]), "+f"(c[3])
        : "r"(a[0]), "r"(a[1]), "r"(a[2]), "r"(a[3]), "r"(b[0]), "r"(b[1]));
}

// ============================================================
// Kernel 0: fused prepass (3 sections by blockIdx.x)
// ============================================================
__global__ void __launch_bounds__(256)
prep_kernel(const float* __restrict__ x, const float* __restrict__ w)
{
    const size_t blk = blockIdx.x;
    if (blk < NPA) {
        size_t idx = blk * 256 + threadIdx.x;
        int pos = (int)(idx & 255);
        size_t bp = idx >> 8;
        int pg = (int)(bp & 1023);
        int b  = (int)(bp >> 10);
        int r = pos >> 4, c = pos & 15;
        float v0 = 0.f, v1 = 0.f;
        if (r >= 1 && r <= 14 && c >= 1 && c <= 14) {
            const float* src = x + ((size_t)b * CIN + 2 * pg) * HWSZ + (r - 1) * WW + (c - 1);
            v0 = src[0];
            v1 = src[HWSZ];
        }
        g_xph[idx] = pack_h2(v0, v1);
    } else if (blk < NPA + NPB) {
        size_t idx = (blk - NPA) * 256 + threadIdx.x;
        int j = (int)(idx % 104);
        size_t bc = idx / 104;
        int p0 = 2 * j, p1 = 2 * j + 1;
        const float* src = x + bc * HWSZ;
        float v0 = (p0 < HWSZ) ? src[p0] : 0.f;
        float v1 = (p1 < HWSZ) ? src[p1] : 0.f;
        g_xe[idx] = pack_h2(v0, v1);
    } else {
        int idx = (int)(blk - NPA - NPB) * 256 + threadIdx.x;
        int o   = idx & 31;
        int kp  = (idx >> 5) & 7;
        int tap = (idx >> 8) % 9;
        int ch  = idx / (9 * 8 * 32);
        int ci0 = ch * 16 + 2 * kp;
        float v0 = w[(size_t)o * (CIN * 9) + (size_t)ci0 * 9 + tap];
        float v1 = w[(size_t)o * (CIN * 9) + (size_t)(ci0 + 1) * 9 + tap];
        g_wt2h[idx] = pack_h2(v0, v1);
    }
}

// ============================================================
// Kernel 1: conv via fp16 implicit GEMM. grid (8, 64). (unchanged)
// ============================================================
__constant__ int TAPD[9] = {0, 1, 2, 16, 17, 18, 32, 33, 34};

__global__ void __launch_bounds__(256)
conv_kernel()
{
    extern __shared__ uint32_t csm[];
    const uint32_t sb = smem_u32(csm);
    const int qx  = blockIdx.x;
    const int b   = blockIdx.y;
    const int tid = threadIdx.x;
    const int wz  = tid >> 5;
    const int lane = tid & 31;
    const int qm = lane >> 2, qk = lane & 3;

    int  ib[2][2];
    bool pv[2][2];
    #pragma unroll
    for (int t = 0; t < 2; t++) {
        #pragma unroll
        for (int h = 0; h < 2; h++) {
            int p = (wz * 2 + t) * 16 + qm + h * 8;
            bool v = p < HWSZ;
            int pr = v ? p / 14 : 0, pc = v ? p % 14 : 0;
            ib[t][h] = pr * 16 + pc;
            pv[t][h] = v;
        }
    }

    auto prefetch = [&](int ch, int pbuf) {
        const uint32_t xbuf = sb + (uint32_t)pbuf * (CV_STAGE_U32 * 4);
        const uint32_t wbuf = xbuf + CV_XS_U32 * 4;
        const int pg0 = qx * 128 + ch * 8;
        const int chg = qx * CV_NCH + ch;
        #pragma unroll
        for (int q = tid; q < 512; q += 256) {
            int kp = q >> 6, j = q & 63;
            cp_async16(xbuf + (uint32_t)(kp * CV_XSTR + j * 4) * 4,
                       g_xph + ((size_t)(b * 1024 + pg0 + kp)) * 256 + j * 4);
        }
        for (int q = tid; q < 576; q += 256) {
            int tap = q / 64;
            int kp  = (q >> 3) & 7;
            int oq  = q & 7;
            cp_async16(wbuf + (uint32_t)(tap * CV_WTAP + kp * CV_WSTR + oq * 4) * 4,
                       g_wt2h + ((size_t)(chg * 9 + tap) * 8 + kp) * 32 + oq * 4);
        }
    };

    float acc[2][4][4];
    #pragma unroll
    for (int t = 0; t < 2; t++)
        #pragma unroll
        for (int n = 0; n < 4; n++)
            #pragma unroll
            for (int i = 0; i < 4; i++) acc[t][n][i] = 0.f;

    prefetch(0, 0);
    cp_commit();

    #pragma unroll 1
    for (int ch = 0; ch < CV_NCH; ch++) {
        if (ch + 1 < CV_NCH) {
            prefetch(ch + 1, (ch + 1) & 1);
            cp_commit();
            cp_wait<1>();
        } else {
            cp_wait<0>();
        }
        __syncthreads();

        const uint32_t* Xs = csm + (ch & 1) * CV_STAGE_U32;
        const uint32_t* Ws = Xs + CV_XS_U32;

        #pragma unroll
        for (int tap = 0; tap < 9; tap++) {
            const int d = TAPD[tap];
            uint32_t a[2][4];
            #pragma unroll
            for (int t = 0; t < 2; t++) {
                a[t][0] = Xs[qk * CV_XSTR + ib[t][0] + d];
                a[t][1] = Xs[qk * CV_XSTR + ib[t][1] + d];
                a[t][2] = Xs[(qk + 4) * CV_XSTR + ib[t][0] + d];
                a[t][3] = Xs[(qk + 4) * CV_XSTR + ib[t][1] + d];
            }
            #pragma unroll
            for (int nt = 0; nt < 4; nt++) {
                uint32_t bf[2];
                bf[0] = Ws[tap * CV_WTAP + qk * CV_WSTR + nt * 8 + qm];
                bf[1] = Ws[tap * CV_WTAP + (qk + 4) * CV_WSTR + nt * 8 + qm];
                mma_f16(acc[0][nt], a[0], bf);
                mma_f16(acc[1][nt], a[1], bf);
            }
        }
        __syncthreads();
    }

    float* dst = g_amp + ((size_t)qx * BB + b) * (HWSZ * COUT);
    #pragma unroll
    for (int t = 0; t < 2; t++) {
        #pragma unroll
        for (int h = 0; h < 2; h++) {
            if (!pv[t][h]) continue;
            int p = (wz * 2 + t) * 16 + qm + h * 8;
            #pragma unroll
            for (int nt = 0; nt < 4; nt++) {
                *(float2*)(dst + p * COUT + nt * 8 + 2 * qk) =
                    make_float2(acc[t][nt][h * 2], acc[t][nt][h * 2 + 1]);
            }
        }
    }
}

// ============================================================
// Kernel 2: einsum (fp16 mma, K=208) with inline am partial-reduce. (unchanged)
// ============================================================
__global__ void __launch_bounds__(256)
einsum_kernel(const float* __restrict__ bias)
{
    extern __shared__ uint32_t esm[];
    const uint32_t sb = smem_u32(esm);

    const int mt  = blockIdx.x;
    const int b   = blockIdx.y;
    const int tid = threadIdx.x;
    const int wz  = tid >> 5;
    const int lane = tid & 31;
    const int qm = lane >> 2, qk = lane & 3;
    const int mh = wz >> 2, nt = wz & 3;
    const int i0 = mt * 256;

    auto prefetch_x = [&](int ch) {
        const uint32_t xbuf = sb + (uint32_t)((32 + 32 * (ch & 1)) * EM_STRU) * 4;
        for (int q = tid; q < 832; q += 256) {
            int row = q / 26, j = q % 26;
            cp_async16(xbuf + (uint32_t)(row * EM_STRU + j * 4) * 4,
                       g_xe + (size_t)(b * CIN + i0 + ch * 32 + row) * 104 + j * 4);
        }
    };

    prefetch_x(0);
    cp_commit();

    {
        const size_t QSTR = (size_t)BB * HWSZ * COUT;
        const size_t base = (size_t)b * (HWSZ * COUT);
        for (int e = tid; e < 32 * 104; e += 256) {
            int o = e & 31, j = e >> 5;
            float s0 = 0.f, s1 = 0.f;
            int p0 = 2 * j, p1 = p0 + 1;
            if (p0 < HWSZ) {
                s0 = bias[o];
                #pragma unroll
                for (int q = 0; q < CV_QX; q++) s0 += g_amp[q * QSTR + base + (size_t)p0 * COUT + o];
            }
            if (p1 < HWSZ) {
                s1 = bias[o];
                #pragma unroll
                for (int q = 0; q < CV_QX; q++) s1 += g_amp[q * QSTR + base + (size_t)p1 * COUT + o];
            }
            esm[o * EM_STRU + j] = pack_h2(s0, s1);
        }
    }

    const float inv = 1.f / (float)HWSZ;

    #pragma unroll 1
    for (int ch = 0; ch < 8; ch++) {
        if (ch + 1 < 8) {
            prefetch_x(ch + 1);
            cp_commit();
            cp_wait<1>();
        } else {
            cp_wait<0>();
        }
        __syncthreads();

        const int arow0 = (32 + 32 * (ch & 1) + mh * 16 + qm) * EM_STRU;
        const int brow0 = (nt * 8 + qm) * EM_STRU;

        float acc[4] = {0.f, 0.f, 0.f, 0.f};
        #pragma unroll
        for (int ks = 0; ks < 13; ks++) {
            const int k0 = ks * 8;
            uint32_t a[4], bf[2];
            a[0] = esm[arow0 + k0 + qk];
            a[1] = esm[arow0 + 8 * EM_STRU + k0 + qk];
            a[2] = esm[arow0 + k0 + 4 + qk];
            a[3] = esm[arow0 + 8 * EM_STRU + k0 + 4 + qk];
            bf[0] = esm[brow0 + k0 + qk];
            bf[1] = esm[brow0 + k0 + 4 + qk];
            mma_f16(acc, a, bf);
        }

        int i = i0 + ch * 32 + mh * 16 + qm;
        int o = nt * 8 + 2 * qk;
        size_t k0h = ((size_t)b * FEAT + (size_t)i * COUT + o) >> 1;
        g_feath[k0h] = pack_h2(acc[0] * inv, acc[1] * inv);
        size_t k1h = ((size_t)b * FEAT + (size_t)(i + 8) * COUT + o) >> 1;
        g_feath[k1h] = pack_h2(acc[2] * inv, acc[3] * inv);
        __syncthreads();
    }
}

// ============================================================
// Kernel 3: fc6 partials, fp16 mma, M=64 tiles, 4-stage pipeline, 3 CTAs/SM.
// grid (16, 32), block 256 (8 warps: m-tile = wz>>1, n-half = wz&1).
// ============================================================
__global__ void __launch_bounds__(256, 3)
fc6_kernel(const float* __restrict__ w6)
{
    extern __shared__ uint32_t fsm[];
    const uint32_t sb = smem_u32(fsm);

    const int mt  = blockIdx.x;
    const int kt  = blockIdx.y;
    const int tid = threadIdx.x;
    const int wz  = tid >> 5;
    const int lane = tid & 31;
    const int qm = lane >> 2, qk = lane & 3;
    const int mtw = wz >> 1;              // 0..3: 16-row tile
    const int nh  = wz & 1;               // 0..1: batch half

    const int    mbase = mt * 64;
    const size_t kbase = (size_t)kt * FC6_KPER;

    const int arow = tid >> 2, akoff = (tid & 3) * 8;    // floats
    const int brow = tid >> 2, bu = (tid & 3) * 4;       // u32
    const float*    ga0 = w6 + (size_t)(mbase + arow) * FEAT + kbase + akoff;
    const uint32_t* gb0 = g_feath + ((size_t)brow * FEAT + kbase) / 2 + bu;

    auto prefetch = [&](int ch) {
        const int st = ch & 3;
        const uint32_t abuf = sb + (uint32_t)st * (STAGE_U32 * 4);
        const uint32_t bbuf = abuf + A_U32 * 4;
        const float* ga = ga0 + (size_t)ch * FC6_KC;
        const uint32_t adst = abuf + (uint32_t)(arow * F6_ASTR + akoff) * 4;
        cp_async16(adst,      ga);
        cp_async16(adst + 16, ga + 4);
        const uint32_t* gb = gb0 + (size_t)ch * (FC6_KC / 2);
        cp_async16(bbuf + (uint32_t)(brow * F6_BSTR + bu) * 4, gb);
    };

    float acc[4][4];
    #pragma unroll
    for (int j = 0; j < 4; j++)
        #pragma unroll
        for (int r = 0; r < 4; r++) acc[j][r] = 0.f;

    prefetch(0); cp_commit();
    prefetch(1); cp_commit();
    prefetch(2); cp_commit();

    #pragma unroll 1
    for (int ch = 0; ch < FC6_NCHUNK; ch++) {
        if (ch + 3 < FC6_NCHUNK) {
            prefetch(ch + 3);
            cp_commit();
            cp_wait<3>();
        } else if (ch + 2 < FC6_NCHUNK) {
            cp_wait<2>();
        } else if (ch + 1 < FC6_NCHUNK) {
            cp_wait<1>();
        } else {
            cp_wait<0>();
        }
        __syncthreads();

        const float*    As = (const float*)(fsm + (ch & 3) * STAGE_U32);
        const uint32_t* Bs = fsm + (ch & 3) * STAGE_U32 + A_U32;
        const int m0 = mtw * 16;

        #pragma unroll
        for (int s = 0; s < 2; s++) {
            const int kb = s * 16;
            uint32_t a[4];
            {
                float2 v0 = *(const float2*)(As + (m0 + qm) * F6_ASTR + kb + 2 * qk);
                float2 v1 = *(const float2*)(As + (m0 + qm + 8) * F6_ASTR + kb + 2 * qk);
                float2 v2 = *(const float2*)(As + (m0 + qm) * F6_ASTR + kb + 8 + 2 * qk);
                float2 v3 = *(const float2*)(As + (m0 + qm + 8) * F6_ASTR + kb + 8 + 2 * qk);
                a[0] = pack_h2(v0.x, v0.y);
                a[1] = pack_h2(v1.x, v1.y);
                a[2] = pack_h2(v2.x, v2.y);
                a[3] = pack_h2(v3.x, v3.y);
            }
            #pragma unroll
            for (int j = 0; j < 4; j++) {
                const int nt = nh * 4 + j;
                uint32_t bf[2];
                bf[0] = Bs[(nt * 8 + qm) * F6_BSTR + s * 8 + qk];
                bf[1] = Bs[(nt * 8 + qm) * F6_BSTR + s * 8 + qk + 4];
                mma_f16(acc[j], a, bf);
            }
        }
        __syncthreads();
    }

    const int r = mbase + mtw * 16 + qm;
    #pragma unroll
    for (int j = 0; j < 4; j++) {
        int bcol = (nh * 4 + j) * 8 + 2 * qk;
        *(float2*)(g_p6 + ((size_t)kt * REP + r) * BB + bcol) =
            make_float2(acc[j][0], acc[j][1]);
        *(float2*)(g_p6 + ((size_t)kt * REP + r + 8) * BB + bcol) =
            make_float2(acc[j][2], acc[j][3]);
    }
}

// ============================================================
// Kernel 4: reduce fc6 partials + bias + relu -> g_h6
// ============================================================
__global__ void __launch_bounds__(256)
reduce6_kernel(const float* __restrict__ b6)
{
    int idx = blockIdx.x * 256 + threadIdx.x;
    int r = idx >> 6, b = idx & 63;
    float sum = b6[r];
    #pragma unroll 8
    for (int kt = 0; kt < FC6_KT; kt++)
        sum += g_p6[((size_t)kt * REP + r) * BB + b];
    g_h6[(size_t)b * REP + r] = fmaxf(sum, 0.f);
}

// ============================================================
// Kernel 5: fc7 + bias + relu. grid (16 bgroups, 4 r-quarters).
// ============================================================
__global__ void __launch_bounds__(256)
fc7_kernel(const float* __restrict__ w7, const float* __restrict__ b7,
           float* __restrict__ out)
{
    const int b0 = blockIdx.x * 4;
    const int r  = blockIdx.y * 256 + threadIdx.x;
    const int tid = threadIdx.x;

    __shared__ float hs[4][REP];
    for (int t = tid; t < 4 * REP; t += 256)
        hs[t >> 10][t & 1023] = g_h6[(size_t)(b0 + (t >> 10)) * REP + (t & 1023)];
    __syncthreads();

    const float4* wr = (const float4*)(w7 + (size_t)r * REP);
    float s0 = 0.f, s1 = 0.f, s2 = 0.f, s3 = 0.f;
    #pragma unroll 4
    for (int k4 = 0; k4 < REP / 4; k4++) {
        float4 wv = wr[k4];
        float4 h0 = *(const float4*)&hs[0][k4 * 4];
        float4 h1 = *(const float4*)&hs[1][k4 * 4];
        float4 h2 = *(const float4*)&hs[2][k4 * 4];
        float4 h3 = *(const float4*)&hs[3][k4 * 4];
        s0 += wv.x * h0.x + wv.y * h0.y + wv.z * h0.z + wv.w * h0.w;
        s1 += wv.x * h1.x + wv.y * h1.y + wv.z * h1.z + wv.w * h1.w;
        s2 += wv.x * h2.x + wv.y * h2.y + wv.z * h2.z + wv.w * h2.w;
        s3 += wv.x * h3.x + wv.y * h3.y + wv.z * h3.z + wv.w * h3.w;
    }
    float bv = b7[r];
    out[(size_t)(b0 + 0) * REP + r] = fmaxf(s0 + bv, 0.f);
    out[(size_t)(b0 + 1) * REP + r] = fmaxf(s1 + bv, 0.f);
    out[(size_t)(b0 + 2) * REP + r] = fmaxf(s2 + bv, 0.f);
    out[(size_t)(b0 + 3) * REP + r] = fmaxf(s3 + bv, 0.f);
}

// ============================================================
// launch (fc6 is 4th launch -> profiled)
// ============================================================
extern "C" void kernel_launch(void* const* d_in, const int* in_sizes, int n_in,
                              void* d_out, int out_size)
{
    const float* x      = (const float*)d_in[0];
    const float* conv_w = (const float*)d_in[1];
    const float* conv_b = (const float*)d_in[2];
    const float* w6     = (const float*)d_in[3];
    const float* b6     = (const float*)d_in[4];
    const float* w7     = (const float*)d_in[5];
    const float* b7     = (const float*)d_in[6];
    float* out = (float*)d_out;

    cudaFuncSetAttribute(conv_kernel,   cudaFuncAttributeMaxDynamicSharedMemorySize, CONV_SMEM);
    cudaFuncSetAttribute(einsum_kernel, cudaFuncAttributeMaxDynamicSharedMemorySize, EM_SMEM);
    cudaFuncSetAttribute(fc6_kernel,    cudaFuncAttributeMaxDynamicSharedMemorySize, FC6_SMEM);

    unsigned nprep = (unsigned)(NPA + NPB + NPC);
    prep_kernel   <<<dim3(nprep), 256>>>(x, conv_w);
    conv_kernel   <<<dim3(CV_QX, BB), 256, CONV_SMEM>>>();
    einsum_kernel <<<dim3(8, BB), 256, EM_SMEM>>>(conv_b);
    fc6_kernel    <<<dim3(FC6_MT, FC6_KT), 256, FC6_SMEM>>>(w6);
    reduce6_kernel<<<dim3(BB * REP / 256), 256>>>(b6);
    fc7_kernel    <<<dim3(16, 4), 256>>>(w7, b7, out);
}

// round 14
// speedup vs baseline: 1.2374x; 1.0999x over previous
#include <cuda_runtime.h>
#include <cuda_fp16.h>
#include <cstdint>

// ---------------- problem constants ----------------
#define BB    64
#define CIN   2048
#define COUT  32
#define HH    14
#define WW    14
#define HWSZ  196
#define REP   1024
#define FEAT  (CIN*COUT)   // 65536

// ---------------- conv tiling (fp16) ----------------
#define CV_QX      8
#define CV_NCH     16
#define CV_XSTR    264
#define CV_WSTR    40
#define CV_WTAP    (8*CV_WSTR)
#define CV_XS_U32  (8*CV_XSTR)
#define CV_WS_U32  (9*CV_WTAP)
#define CV_STAGE_U32 (CV_XS_U32+CV_WS_U32)
#define CONV_SMEM  (2*CV_STAGE_U32*4)      // 39936 B

// ---------------- einsum tiling (fp16, K=208) ----------------
#define EM_STRU    108
#define EM_SMEM    (96*EM_STRU*4)          // 41472 B

// ---------------- fc6 tiling (fp16 mma, M=64, 3 stages, 4 CTAs/SM) ----------------
#define FC6_MT     16
#define FC6_KT     32
#define FC6_KPER   (FEAT/FC6_KT)           // 2048
#define FC6_KC     32
#define FC6_NCHUNK (FC6_KPER/FC6_KC)       // 64
#define F6_ASTR    40
#define F6_BSTR    20
#define A_U32      (64*F6_ASTR)            // 2560
#define B_U32      (64*F6_BSTR)            // 1280
#define STAGE_U32  (A_U32+B_U32)           // 3840
#define FC6_NSTG   3
#define FC6_SMEM   (FC6_NSTG*STAGE_U32*4)  // 46080 B -> 4 CTAs/SM

// ---------------- prep sections ----------------
#define NPAB (BB*1024)                     // 65536 blocks: (b, cin-pair) fused x prep
#define NPC  (128*9*8*32/256)              // 1152 blocks: weights

// ---------------- scratch (device globals) ----------------
__device__ uint32_t g_xph[(size_t)BB*1024*256];     // conv x canvas half2
__device__ uint32_t g_xe[(size_t)BB*CIN*104];       // einsum x half2, K=208
__device__ uint32_t g_wt2h[128*9*8*32];             // conv weights half2
__device__ float g_amp[(size_t)CV_QX*BB*HWSZ*COUT]; // conv partials [q][b][p][o]
__device__ uint32_t g_feath[(size_t)BB*FEAT/2];     // feat as half2 (k-pairs)
__device__ float g_p6[(size_t)FC6_KT*REP*BB];
__device__ float g_h6[BB*REP];

// ---------------- PTX helpers ----------------
__device__ __forceinline__ uint32_t smem_u32(const void* p) {
    uint32_t a;
    asm("{ .reg .u64 t; cvta.to.shared.u64 t, %1; cvt.u32.u64 %0, t; }" : "=r"(a) : "l"(p));
    return a;
}
__device__ __forceinline__ uint32_t pack_h2(float a, float b) {
    __half2 h = __floats2half2_rn(a, b);
    return *(uint32_t*)&h;
}
__device__ __forceinline__ void cp_async16(uint32_t dst, const void* src) {
    asm volatile("cp.async.cg.shared.global [%0], [%1], 16;" :: "r"(dst), "l"(src) : "memory");
}
__device__ __forceinline__ void cp_commit() {
    asm volatile("cp.async.commit_group;" ::: "memory");
}
template <int N>
__device__ __forceinline__ void cp_wait() {
    asm volatile("cp.async.wait_group %0;" :: "n"(N) : "memory");
}
__device__ __forceinline__ void mma_f16(float* c, const uint32_t* a, const uint32_t* b) {
    asm volatile(
        "mma.sync.aligned.m16n8k16.row.col.f32.f16.f16.f32 "
        "{%0,%1,%2,%3}, {%4,%5,%6,%7}, {%8,%9}, {%0,%1,%2,%3};"
        : "+f"(c[0]), "+f"(c[1]), "+f"(c[2]), "+f"(c[3])
        : "r"(a[0]), "r"(a[1]), "r"(a[2]), "r"(a[3]), "r"(b[0]), "r"(b[1]));
}

// ============================================================
// Kernel 0: fused prepass.
// Blocks [0, NPAB): one (b, cin-pair) each — read x once (2 cins, 392 floats),
//   emit conv canvas (256 half2) AND einsum rows (2 x 104 half2).
// Blocks [NPAB, NPAB+NPC): conv weights half2.
// ============================================================
__global__ void __launch_bounds__(256)
prep_kernel(const float* __restrict__ x, const float* __restrict__ w)
{
    const unsigned blk = blockIdx.x;
    if (blk < NPAB) {
        __shared__ float xs[392];
        const int tid = threadIdx.x;
        const int b  = blk >> 10;
        const int pg = blk & 1023;
        const float4* src = (const float4*)(x + ((size_t)b * CIN + 2 * pg) * HWSZ);
        if (tid < 98) ((float4*)xs)[tid] = src[tid];
        __syncthreads();
        // conv canvas: pos = tid (16x16), border zero
        {
            int r = tid >> 4, c = tid & 15;
            float v0 = 0.f, v1 = 0.f;
            if (r >= 1 && r <= 14 && c >= 1 && c <= 14) {
                int e = (r - 1) * WW + (c - 1);
                v0 = xs[e];
                v1 = xs[196 + e];
            }
            g_xph[(size_t)blk * 256 + tid] = pack_h2(v0, v1);
        }
        // einsum rows: t<208 -> (ci = t/104, j = t%104)
        if (tid < 208) {
            int ci = tid / 104, j = tid - ci * 104;
            int p0 = 2 * j, p1 = p0 + 1;
            float v0 = (p0 < HWSZ) ? xs[ci * HWSZ + p0] : 0.f;
            float v1 = (p1 < HWSZ) ? xs[ci * HWSZ + p1] : 0.f;
            g_xe[((size_t)b * CIN + 2 * pg + ci) * 104 + j] = pack_h2(v0, v1);
        }
    } else {
        int idx = (int)(blk - NPAB) * 256 + threadIdx.x;
        int o   = idx & 31;
        int kp  = (idx >> 5) & 7;
        int tap = (idx >> 8) % 9;
        int ch  = idx / (9 * 8 * 32);
        int ci0 = ch * 16 + 2 * kp;
        float v0 = w[(size_t)o * (CIN * 9) + (size_t)ci0 * 9 + tap];
        float v1 = w[(size_t)o * (CIN * 9) + (size_t)(ci0 + 1) * 9 + tap];
        g_wt2h[idx] = pack_h2(v0, v1);
    }
}

// ============================================================
// Kernel 1: conv via fp16 implicit GEMM. grid (8, 64). (unchanged)
// ============================================================
__constant__ int TAPD[9] = {0, 1, 2, 16, 17, 18, 32, 33, 34};

__global__ void __launch_bounds__(256)
conv_kernel()
{
    extern __shared__ uint32_t csm[];
    const uint32_t sb = smem_u32(csm);
    const int qx  = blockIdx.x;
    const int b   = blockIdx.y;
    const int tid = threadIdx.x;
    const int wz  = tid >> 5;
    const int lane = tid & 31;
    const int qm = lane >> 2, qk = lane & 3;

    int  ib[2][2];
    bool pv[2][2];
    #pragma unroll
    for (int t = 0; t < 2; t++) {
        #pragma unroll
        for (int h = 0; h < 2; h++) {
            int p = (wz * 2 + t) * 16 + qm + h * 8;
            bool v = p < HWSZ;
            int pr = v ? p / 14 : 0, pc = v ? p % 14 : 0;
            ib[t][h] = pr * 16 + pc;
            pv[t][h] = v;
        }
    }

    auto prefetch = [&](int ch, int pbuf) {
        const uint32_t xbuf = sb + (uint32_t)pbuf * (CV_STAGE_U32 * 4);
        const uint32_t wbuf = xbuf + CV_XS_U32 * 4;
        const int pg0 = qx * 128 + ch * 8;
        const int chg = qx * CV_NCH + ch;
        #pragma unroll
        for (int q = tid; q < 512; q += 256) {
            int kp = q >> 6, j = q & 63;
            cp_async16(xbuf + (uint32_t)(kp * CV_XSTR + j * 4) * 4,
                       g_xph + ((size_t)(b * 1024 + pg0 + kp)) * 256 + j * 4);
        }
        for (int q = tid; q < 576; q += 256) {
            int tap = q / 64;
            int kp  = (q >> 3) & 7;
            int oq  = q & 7;
            cp_async16(wbuf + (uint32_t)(tap * CV_WTAP + kp * CV_WSTR + oq * 4) * 4,
                       g_wt2h + ((size_t)(chg * 9 + tap) * 8 + kp) * 32 + oq * 4);
        }
    };

    float acc[2][4][4];
    #pragma unroll
    for (int t = 0; t < 2; t++)
        #pragma unroll
        for (int n = 0; n < 4; n++)
            #pragma unroll
            for (int i = 0; i < 4; i++) acc[t][n][i] = 0.f;

    prefetch(0, 0);
    cp_commit();

    #pragma unroll 1
    for (int ch = 0; ch < CV_NCH; ch++) {
        if (ch + 1 < CV_NCH) {
            prefetch(ch + 1, (ch + 1) & 1);
            cp_commit();
            cp_wait<1>();
        } else {
            cp_wait<0>();
        }
        __syncthreads();

        const uint32_t* Xs = csm + (ch & 1) * CV_STAGE_U32;
        const uint32_t* Ws = Xs + CV_XS_U32;

        #pragma unroll
        for (int tap = 0; tap < 9; tap++) {
            const int d = TAPD[tap];
            uint32_t a[2][4];
            #pragma unroll
            for (int t = 0; t < 2; t++) {
                a[t][0] = Xs[qk * CV_XSTR + ib[t][0] + d];
                a[t][1] = Xs[qk * CV_XSTR + ib[t][1] + d];
                a[t][2] = Xs[(qk + 4) * CV_XSTR + ib[t][0] + d];
                a[t][3] = Xs[(qk + 4) * CV_XSTR + ib[t][1] + d];
            }
            #pragma unroll
            for (int nt = 0; nt < 4; nt++) {
                uint32_t bf[2];
                bf[0] = Ws[tap * CV_WTAP + qk * CV_WSTR + nt * 8 + qm];
                bf[1] = Ws[tap * CV_WTAP + (qk + 4) * CV_WSTR + nt * 8 + qm];
                mma_f16(acc[0][nt], a[0], bf);
                mma_f16(acc[1][nt], a[1], bf);
            }
        }
        __syncthreads();
    }

    float* dst = g_amp + ((size_t)qx * BB + b) * (HWSZ * COUT);
    #pragma unroll
    for (int t = 0; t < 2; t++) {
        #pragma unroll
        for (int h = 0; h < 2; h++) {
            if (!pv[t][h]) continue;
            int p = (wz * 2 + t) * 16 + qm + h * 8;
            #pragma unroll
            for (int nt = 0; nt < 4; nt++) {
                *(float2*)(dst + p * COUT + nt * 8 + 2 * qk) =
                    make_float2(acc[t][nt][h * 2], acc[t][nt][h * 2 + 1]);
            }
        }
    }
}

// ============================================================
// Kernel 2: einsum (fp16 mma, K=208) with inline am partial-reduce. (unchanged)
// ============================================================
__global__ void __launch_bounds__(256)
einsum_kernel(const float* __restrict__ bias)
{
    extern __shared__ uint32_t esm[];
    const uint32_t sb = smem_u32(esm);

    const int mt  = blockIdx.x;
    const int b   = blockIdx.y;
    const int tid = threadIdx.x;
    const int wz  = tid >> 5;
    const int lane = tid & 31;
    const int qm = lane >> 2, qk = lane & 3;
    const int mh = wz >> 2, nt = wz & 3;
    const int i0 = mt * 256;

    auto prefetch_x = [&](int ch) {
        const uint32_t xbuf = sb + (uint32_t)((32 + 32 * (ch & 1)) * EM_STRU) * 4;
        for (int q = tid; q < 832; q += 256) {
            int row = q / 26, j = q % 26;
            cp_async16(xbuf + (uint32_t)(row * EM_STRU + j * 4) * 4,
                       g_xe + (size_t)(b * CIN + i0 + ch * 32 + row) * 104 + j * 4);
        }
    };

    prefetch_x(0);
    cp_commit();

    {
        const size_t QSTR = (size_t)BB * HWSZ * COUT;
        const size_t base = (size_t)b * (HWSZ * COUT);
        for (int e = tid; e < 32 * 104; e += 256) {
            int o = e & 31, j = e >> 5;
            float s0 = 0.f, s1 = 0.f;
            int p0 = 2 * j, p1 = p0 + 1;
            if (p0 < HWSZ) {
                s0 = bias[o];
                #pragma unroll
                for (int q = 0; q < CV_QX; q++) s0 += g_amp[q * QSTR + base + (size_t)p0 * COUT + o];
            }
            if (p1 < HWSZ) {
                s1 = bias[o];
                #pragma unroll
                for (int q = 0; q < CV_QX; q++) s1 += g_amp[q * QSTR + base + (size_t)p1 * COUT + o];
            }
            esm[o * EM_STRU + j] = pack_h2(s0, s1);
        }
    }

    const float inv = 1.f / (float)HWSZ;

    #pragma unroll 1
    for (int ch = 0; ch < 8; ch++) {
        if (ch + 1 < 8) {
            prefetch_x(ch + 1);
            cp_commit();
            cp_wait<1>();
        } else {
            cp_wait<0>();
        }
        __syncthreads();

        const int arow0 = (32 + 32 * (ch & 1) + mh * 16 + qm) * EM_STRU;
        const int brow0 = (nt * 8 + qm) * EM_STRU;

        float acc[4] = {0.f, 0.f, 0.f, 0.f};
        #pragma unroll
        for (int ks = 0; ks < 13; ks++) {
            const int k0 = ks * 8;
            uint32_t a[4], bf[2];
            a[0] = esm[arow0 + k0 + qk];
            a[1] = esm[arow0 + 8 * EM_STRU + k0 + qk];
            a[2] = esm[arow0 + k0 + 4 + qk];
            a[3] = esm[arow0 + 8 * EM_STRU + k0 + 4 + qk];
            bf[0] = esm[brow0 + k0 + qk];
            bf[1] = esm[brow0 + k0 + 4 + qk];
            mma_f16(acc, a, bf);
        }

        int i = i0 + ch * 32 + mh * 16 + qm;
        int o = nt * 8 + 2 * qk;
        size_t k0h = ((size_t)b * FEAT + (size_t)i * COUT + o) >> 1;
        g_feath[k0h] = pack_h2(acc[0] * inv, acc[1] * inv);
        size_t k1h = ((size_t)b * FEAT + (size_t)(i + 8) * COUT + o) >> 1;
        g_feath[k1h] = pack_h2(acc[2] * inv, acc[3] * inv);
        __syncthreads();
    }
}

// ============================================================
// Kernel 3: fc6 partials, fp16 mma, M=64, 3-stage pipeline, 4 CTAs/SM.
// grid (16, 32) = 512 CTAs, fully resident in one wave.
// ============================================================
__global__ void __launch_bounds__(256, 4)
fc6_kernel(const float* __restrict__ w6)
{
    extern __shared__ uint32_t fsm[];
    const uint32_t sb = smem_u32(fsm);

    const int mt  = blockIdx.x;
    const int kt  = blockIdx.y;
    const int tid = threadIdx.x;
    const int wz  = tid >> 5;
    const int lane = tid & 31;
    const int qm = lane >> 2, qk = lane & 3;
    const int mtw = wz >> 1;
    const int nh  = wz & 1;

    const int    mbase = mt * 64;
    const size_t kbase = (size_t)kt * FC6_KPER;

    const int arow = tid >> 2, akoff = (tid & 3) * 8;
    const int brow = tid >> 2, bu = (tid & 3) * 4;
    const float*    ga0 = w6 + (size_t)(mbase + arow) * FEAT + kbase + akoff;
    const uint32_t* gb0 = g_feath + ((size_t)brow * FEAT + kbase) / 2 + bu;

    auto prefetch = [&](int ch) {
        const int st = ch % FC6_NSTG;
        const uint32_t abuf = sb + (uint32_t)st * (STAGE_U32 * 4);
        const uint32_t bbuf = abuf + A_U32 * 4;
        const float* ga = ga0 + (size_t)ch * FC6_KC;
        const uint32_t adst = abuf + (uint32_t)(arow * F6_ASTR + akoff) * 4;
        cp_async16(adst,      ga);
        cp_async16(adst + 16, ga + 4);
        const uint32_t* gb = gb0 + (size_t)ch * (FC6_KC / 2);
        cp_async16(bbuf + (uint32_t)(brow * F6_BSTR + bu) * 4, gb);
    };

    float acc[4][4];
    #pragma unroll
    for (int j = 0; j < 4; j++)
        #pragma unroll
        for (int r = 0; r < 4; r++) acc[j][r] = 0.f;

    prefetch(0); cp_commit();
    prefetch(1); cp_commit();

    #pragma unroll 1
    for (int ch = 0; ch < FC6_NCHUNK; ch++) {
        if (ch + 2 < FC6_NCHUNK) {
            prefetch(ch + 2);
            cp_commit();
            cp_wait<2>();
        } else if (ch + 1 < FC6_NCHUNK) {
            cp_wait<1>();
        } else {
            cp_wait<0>();
        }
        __syncthreads();

        const float*    As = (const float*)(fsm + (ch % FC6_NSTG) * STAGE_U32);
        const uint32_t* Bs = fsm + (ch % FC6_NSTG) * STAGE_U32 + A_U32;
        const int m0 = mtw * 16;

        #pragma unroll
        for (int s = 0; s < 2; s++) {
            const int kb = s * 16;
            uint32_t a[4];
            {
                float2 v0 = *(const float2*)(As + (m0 + qm) * F6_ASTR + kb + 2 * qk);
                float2 v1 = *(const float2*)(As + (m0 + qm + 8) * F6_ASTR + kb + 2 * qk);
                float2 v2 = *(const float2*)(As + (m0 + qm) * F6_ASTR + kb + 8 + 2 * qk);
                float2 v3 = *(const float2*)(As + (m0 + qm + 8) * F6_ASTR + kb + 8 + 2 * qk);
                a[0] = pack_h2(v0.x, v0.y);
                a[1] = pack_h2(v1.x, v1.y);
                a[2] = pack_h2(v2.x, v2.y);
                a[3] = pack_h2(v3.x, v3.y);
            }
            #pragma unroll
            for (int j = 0; j < 4; j++) {
                const int nt = nh * 4 + j;
                uint32_t bf[2];
                bf[0] = Bs[(nt * 8 + qm) * F6_BSTR + s * 8 + qk];
                bf[1] = Bs[(nt * 8 + qm) * F6_BSTR + s * 8 + qk + 4];
                mma_f16(acc[j], a, bf);
            }
        }
        __syncthreads();
    }

    const int r = mbase + mtw * 16 + qm;
    #pragma unroll
    for (int j = 0; j < 4; j++) {
        int bcol = (nh * 4 + j) * 8 + 2 * qk;
        *(float2*)(g_p6 + ((size_t)kt * REP + r) * BB + bcol) =
            make_float2(acc[j][0], acc[j][1]);
        *(float2*)(g_p6 + ((size_t)kt * REP + r + 8) * BB + bcol) =
            make_float2(acc[j][2], acc[j][3]);
    }
}

// ============================================================
// Kernel 4: reduce fc6 partials + bias + relu -> g_h6
// ============================================================
__global__ void __launch_bounds__(256)
reduce6_kernel(const float* __restrict__ b6)
{
    int idx = blockIdx.x * 256 + threadIdx.x;
    int r = idx >> 6, b = idx & 63;
    float sum = b6[r];
    #pragma unroll 8
    for (int kt = 0; kt < FC6_KT; kt++)
        sum += g_p6[((size_t)kt * REP + r) * BB + b];
    g_h6[(size_t)b * REP + r] = fmaxf(sum, 0.f);
}

// ============================================================
// Kernel 5: fc7 + bias + relu. grid (16 bgroups, 4 r-quarters).
// ============================================================
__global__ void __launch_bounds__(256)
fc7_kernel(const float* __restrict__ w7, const float* __restrict__ b7,
           float* __restrict__ out)
{
    const int b0 = blockIdx.x * 4;
    const int r  = blockIdx.y * 256 + threadIdx.x;
    const int tid = threadIdx.x;

    __shared__ float hs[4][REP];
    for (int t = tid; t < 4 * REP; t += 256)
        hs[t >> 10][t & 1023] = g_h6[(size_t)(b0 + (t >> 10)) * REP + (t & 1023)];
    __syncthreads();

    const float4* wr = (const float4*)(w7 + (size_t)r * REP);
    float s0 = 0.f, s1 = 0.f, s2 = 0.f, s3 = 0.f;
    #pragma unroll 4
    for (int k4 = 0; k4 < REP / 4; k4++) {
        float4 wv = wr[k4];
        float4 h0 = *(const float4*)&hs[0][k4 * 4];
        float4 h1 = *(const float4*)&hs[1][k4 * 4];
        float4 h2 = *(const float4*)&hs[2][k4 * 4];
        float4 h3 = *(const float4*)&hs[3][k4 * 4];
        s0 += wv.x * h0.x + wv.y * h0.y + wv.z * h0.z + wv.w * h0.w;
        s1 += wv.x * h1.x + wv.y * h1.y + wv.z * h1.z + wv.w * h1.w;
        s2 += wv.x * h2.x + wv.y * h2.y + wv.z * h2.z + wv.w * h2.w;
        s3 += wv.x * h3.x + wv.y * h3.y + wv.z * h3.z + wv.w * h3.w;
    }
    float bv = b7[r];
    out[(size_t)(b0 + 0) * REP + r] = fmaxf(s0 + bv, 0.f);
    out[(size_t)(b0 + 1) * REP + r] = fmaxf(s1 + bv, 0.f);
    out[(size_t)(b0 + 2) * REP + r] = fmaxf(s2 + bv, 0.f);
    out[(size_t)(b0 + 3) * REP + r] = fmaxf(s3 + bv, 0.f);
}

// ============================================================
// launch (fc6 is 4th launch -> profiled)
// ============================================================
extern "C" void kernel_launch(void* const* d_in, const int* in_sizes, int n_in,
                              void* d_out, int out_size)
{
    const float* x      = (const float*)d_in[0];
    const float* conv_w = (const float*)d_in[1];
    const float* conv_b = (const float*)d_in[2];
    const float* w6     = (const float*)d_in[3];
    const float* b6     = (const float*)d_in[4];
    const float* w7     = (const float*)d_in[5];
    const float* b7     = (const float*)d_in[6];
    float* out = (float*)d_out;

    cudaFuncSetAttribute(conv_kernel,   cudaFuncAttributeMaxDynamicSharedMemorySize, CONV_SMEM);
    cudaFuncSetAttribute(einsum_kernel, cudaFuncAttributeMaxDynamicSharedMemorySize, EM_SMEM);
    cudaFuncSetAttribute(fc6_kernel,    cudaFuncAttributeMaxDynamicSharedMemorySize, FC6_SMEM);

    prep_kernel   <<<dim3(NPAB + NPC), 256>>>(x, conv_w);
    conv_kernel   <<<dim3(CV_QX, BB), 256, CONV_SMEM>>>();
    einsum_kernel <<<dim3(8, BB), 256, EM_SMEM>>>(conv_b);
    fc6_kernel    <<<dim3(FC6_MT, FC6_KT), 256, FC6_SMEM>>>(w6);
    reduce6_kernel<<<dim3(BB * REP / 256), 256>>>(b6);
    fc7_kernel    <<<dim3(16, 4), 256>>>(w7, b7, out);
}

// round 15
// speedup vs baseline: 1.3363x; 1.0799x over previous
#include <cuda_runtime.h>
#include <cuda_fp16.h>
#include <cstdint>

// ---------------- problem constants ----------------
#define BB    64
#define CIN   2048
#define COUT  32
#define HH    14
#define WW    14
#define HWSZ  196
#define REP   1024
#define FEAT  (CIN*COUT)   // 65536

// ---------------- conv tiling (fp16) ----------------
#define CV_QX      8
#define CV_NCH     16
#define CV_XSTR    264
#define CV_WSTR    40
#define CV_WTAP    (8*CV_WSTR)
#define CV_XS_U32  (8*CV_XSTR)
#define CV_WS_U32  (9*CV_WTAP)
#define CV_STAGE_U32 (CV_XS_U32+CV_WS_U32)
#define CONV_SMEM  (2*CV_STAGE_U32*4)      // 39936 B

// ---------------- einsum tiling (fp16, K=208) ----------------
#define EM_STRU    108
#define EM_SMEM    (96*EM_STRU*4)          // 41472 B

// ---------------- fc6 tiling (fp16 mma, M=64, 3 stages, 4 CTAs/SM) ----------------
#define FC6_MT     16
#define FC6_KT     32
#define FC6_KPER   (FEAT/FC6_KT)           // 2048
#define FC6_KC     32
#define FC6_NCHUNK (FC6_KPER/FC6_KC)       // 64
#define F6_ASTR    40
#define F6_BSTR    20
#define A_U32      (64*F6_ASTR)            // 2560
#define B_U32      (64*F6_BSTR)            // 1280
#define STAGE_U32  (A_U32+B_U32)           // 3840
#define FC6_NSTG   3
#define FC6_SMEM   (FC6_NSTG*STAGE_U32*4)  // 46080 B -> 4 CTAs/SM

// ---------------- scratch (device globals) ----------------
__device__ uint32_t g_xph[(size_t)BB*1024*256];     // conv x canvas half2
__device__ uint32_t g_xe[(size_t)BB*CIN*104];       // einsum x half2, K=208
__device__ uint32_t g_wt2h[128*9*8*32];             // conv weights half2
__device__ float g_amp[(size_t)CV_QX*BB*HWSZ*COUT]; // conv partials [q][b][p][o]
__device__ uint32_t g_feath[(size_t)BB*FEAT/2];     // feat as half2 (k-pairs)
__device__ float g_p6[(size_t)FC6_KT*REP*BB];
__device__ float g_h6[BB*REP];

// ---------------- PTX helpers ----------------
__device__ __forceinline__ uint32_t smem_u32(const void* p) {
    uint32_t a;
    asm("{ .reg .u64 t; cvta.to.shared.u64 t, %1; cvt.u32.u64 %0, t; }" : "=r"(a) : "l"(p));
    return a;
}
__device__ __forceinline__ uint32_t pack_h2(float a, float b) {
    __half2 h = __floats2half2_rn(a, b);
    return *(uint32_t*)&h;
}
__device__ __forceinline__ void cp_async16(uint32_t dst, const void* src) {
    asm volatile("cp.async.cg.shared.global [%0], [%1], 16;" :: "r"(dst), "l"(src) : "memory");
}
__device__ __forceinline__ void cp_commit() {
    asm volatile("cp.async.commit_group;" ::: "memory");
}
template <int N>
__device__ __forceinline__ void cp_wait() {
    asm volatile("cp.async.wait_group %0;" :: "n"(N) : "memory");
}
__device__ __forceinline__ void mma_f16(float* c, const uint32_t* a, const uint32_t* b) {
    asm volatile(
        "mma.sync.aligned.m16n8k16.row.col.f32.f16.f16.f32 "
        "{%0,%1,%2,%3}, {%4,%5,%6,%7}, {%8,%9}, {%0,%1,%2,%3};"
        : "+f"(c[0]), "+f"(c[1]), "+f"(c[2]), "+f"(c[3])
        : "r"(a[0]), "r"(a[1]), "r"(a[2]), "r"(a[3]), "r"(b[0]), "r"(b[1]));
}

// ============================================================
// Kernel 0a: conv weights half2  [chunk][tap][kpair][o]
// ============================================================
__global__ void __launch_bounds__(256)
prepw_kernel(const float* __restrict__ w)
{
    int idx = blockIdx.x * 256 + threadIdx.x;
    if (idx >= 128 * 9 * 8 * 32) return;
    int o   = idx & 31;
    int kp  = (idx >> 5) & 7;
    int tap = (idx >> 8) % 9;
    int ch  = idx / (9 * 8 * 32);
    int ci0 = ch * 16 + 2 * kp;
    float v0 = w[(size_t)o * (CIN * 9) + (size_t)ci0 * 9 + tap];
    float v1 = w[(size_t)o * (CIN * 9) + (size_t)(ci0 + 1) * 9 + tap];
    g_wt2h[idx] = pack_h2(v0, v1);
}

// ============================================================
// Kernel 0b: x prepass, wide blocks.
// grid 8192: blk -> (b = blk>>7, g8 = blk&127) = 16 cins (8 pairs).
// Emits conv canvas (8 x 256 half2) + einsum rows (16 x 104 half2).
// ============================================================
__global__ void __launch_bounds__(256)
prepx_kernel(const float* __restrict__ x)
{
    __shared__ float xs[16 * HWSZ];            // 3136 floats
    const int tid = threadIdx.x;
    const int b   = blockIdx.x >> 7;
    const int g8  = blockIdx.x & 127;

    const float4* src = (const float4*)(x + ((size_t)b * CIN + 16 * g8) * HWSZ);
    #pragma unroll
    for (int t = tid; t < 784; t += 256) ((float4*)xs)[t] = src[t];
    __syncthreads();

    // conv canvas: 8 pairs x 256 positions (coalesced 1KB stores per pair)
    {
        int r = tid >> 4, c = tid & 15;
        bool inb = (r >= 1 && r <= 14 && c >= 1 && c <= 14);
        int e = inb ? (r - 1) * WW + (c - 1) : 0;
        uint32_t* dst = g_xph + ((size_t)b * 1024 + g8 * 8) * 256 + tid;
        #pragma unroll
        for (int pp = 0; pp < 8; pp++) {
            float v0 = inb ? xs[(2 * pp) * HWSZ + e] : 0.f;
            float v1 = inb ? xs[(2 * pp + 1) * HWSZ + e] : 0.f;
            dst[pp * 256] = pack_h2(v0, v1);
        }
    }
    // einsum rows: 16 cins x 104 half2
    for (int t = tid; t < 16 * 104; t += 256) {
        int ci = t / 104, j = t - ci * 104;
        int p0 = 2 * j, p1 = p0 + 1;
        float v0 = (p0 < HWSZ) ? xs[ci * HWSZ + p0] : 0.f;
        float v1 = (p1 < HWSZ) ? xs[ci * HWSZ + p1] : 0.f;
        g_xe[((size_t)b * CIN + 16 * g8 + ci) * 104 + j] = pack_h2(v0, v1);
    }
}

// ============================================================
// Kernel 1: conv via fp16 implicit GEMM. grid (8, 64). (unchanged)
// ============================================================
__constant__ int TAPD[9] = {0, 1, 2, 16, 17, 18, 32, 33, 34};

__global__ void __launch_bounds__(256)
conv_kernel()
{
    extern __shared__ uint32_t csm[];
    const uint32_t sb = smem_u32(csm);
    const int qx  = blockIdx.x;
    const int b   = blockIdx.y;
    const int tid = threadIdx.x;
    const int wz  = tid >> 5;
    const int lane = tid & 31;
    const int qm = lane >> 2, qk = lane & 3;

    int  ib[2][2];
    bool pv[2][2];
    #pragma unroll
    for (int t = 0; t < 2; t++) {
        #pragma unroll
        for (int h = 0; h < 2; h++) {
            int p = (wz * 2 + t) * 16 + qm + h * 8;
            bool v = p < HWSZ;
            int pr = v ? p / 14 : 0, pc = v ? p % 14 : 0;
            ib[t][h] = pr * 16 + pc;
            pv[t][h] = v;
        }
    }

    auto prefetch = [&](int ch, int pbuf) {
        const uint32_t xbuf = sb + (uint32_t)pbuf * (CV_STAGE_U32 * 4);
        const uint32_t wbuf = xbuf + CV_XS_U32 * 4;
        const int pg0 = qx * 128 + ch * 8;
        const int chg = qx * CV_NCH + ch;
        #pragma unroll
        for (int q = tid; q < 512; q += 256) {
            int kp = q >> 6, j = q & 63;
            cp_async16(xbuf + (uint32_t)(kp * CV_XSTR + j * 4) * 4,
                       g_xph + ((size_t)(b * 1024 + pg0 + kp)) * 256 + j * 4);
        }
        for (int q = tid; q < 576; q += 256) {
            int tap = q / 64;
            int kp  = (q >> 3) & 7;
            int oq  = q & 7;
            cp_async16(wbuf + (uint32_t)(tap * CV_WTAP + kp * CV_WSTR + oq * 4) * 4,
                       g_wt2h + ((size_t)(chg * 9 + tap) * 8 + kp) * 32 + oq * 4);
        }
    };

    float acc[2][4][4];
    #pragma unroll
    for (int t = 0; t < 2; t++)
        #pragma unroll
        for (int n = 0; n < 4; n++)
            #pragma unroll
            for (int i = 0; i < 4; i++) acc[t][n][i] = 0.f;

    prefetch(0, 0);
    cp_commit();

    #pragma unroll 1
    for (int ch = 0; ch < CV_NCH; ch++) {
        if (ch + 1 < CV_NCH) {
            prefetch(ch + 1, (ch + 1) & 1);
            cp_commit();
            cp_wait<1>();
        } else {
            cp_wait<0>();
        }
        __syncthreads();

        const uint32_t* Xs = csm + (ch & 1) * CV_STAGE_U32;
        const uint32_t* Ws = Xs + CV_XS_U32;

        #pragma unroll
        for (int tap = 0; tap < 9; tap++) {
            const int d = TAPD[tap];
            uint32_t a[2][4];
            #pragma unroll
            for (int t = 0; t < 2; t++) {
                a[t][0] = Xs[qk * CV_XSTR + ib[t][0] + d];
                a[t][1] = Xs[qk * CV_XSTR + ib[t][1] + d];
                a[t][2] = Xs[(qk + 4) * CV_XSTR + ib[t][0] + d];
                a[t][3] = Xs[(qk + 4) * CV_XSTR + ib[t][1] + d];
            }
            #pragma unroll
            for (int nt = 0; nt < 4; nt++) {
                uint32_t bf[2];
                bf[0] = Ws[tap * CV_WTAP + qk * CV_WSTR + nt * 8 + qm];
                bf[1] = Ws[tap * CV_WTAP + (qk + 4) * CV_WSTR + nt * 8 + qm];
                mma_f16(acc[0][nt], a[0], bf);
                mma_f16(acc[1][nt], a[1], bf);
            }
        }
        __syncthreads();
    }

    float* dst = g_amp + ((size_t)qx * BB + b) * (HWSZ * COUT);
    #pragma unroll
    for (int t = 0; t < 2; t++) {
        #pragma unroll
        for (int h = 0; h < 2; h++) {
            if (!pv[t][h]) continue;
            int p = (wz * 2 + t) * 16 + qm + h * 8;
            #pragma unroll
            for (int nt = 0; nt < 4; nt++) {
                *(float2*)(dst + p * COUT + nt * 8 + 2 * qk) =
                    make_float2(acc[t][nt][h * 2], acc[t][nt][h * 2 + 1]);
            }
        }
    }
}

// ============================================================
// Kernel 2: einsum (fp16 mma, K=208) with inline am partial-reduce. (unchanged)
// 4th launch -> profiled this round.
// ============================================================
__global__ void __launch_bounds__(256)
einsum_kernel(const float* __restrict__ bias)
{
    extern __shared__ uint32_t esm[];
    const uint32_t sb = smem_u32(esm);

    const int mt  = blockIdx.x;
    const int b   = blockIdx.y;
    const int tid = threadIdx.x;
    const int wz  = tid >> 5;
    const int lane = tid & 31;
    const int qm = lane >> 2, qk = lane & 3;
    const int mh = wz >> 2, nt = wz & 3;
    const int i0 = mt * 256;

    auto prefetch_x = [&](int ch) {
        const uint32_t xbuf = sb + (uint32_t)((32 + 32 * (ch & 1)) * EM_STRU) * 4;
        for (int q = tid; q < 832; q += 256) {
            int row = q / 26, j = q % 26;
            cp_async16(xbuf + (uint32_t)(row * EM_STRU + j * 4) * 4,
                       g_xe + (size_t)(b * CIN + i0 + ch * 32 + row) * 104 + j * 4);
        }
    };

    prefetch_x(0);
    cp_commit();

    {
        const size_t QSTR = (size_t)BB * HWSZ * COUT;
        const size_t base = (size_t)b * (HWSZ * COUT);
        for (int e = tid; e < 32 * 104; e += 256) {
            int o = e & 31, j = e >> 5;
            float s0 = 0.f, s1 = 0.f;
            int p0 = 2 * j, p1 = p0 + 1;
            if (p0 < HWSZ) {
                s0 = bias[o];
                #pragma unroll
                for (int q = 0; q < CV_QX; q++) s0 += g_amp[q * QSTR + base + (size_t)p0 * COUT + o];
            }
            if (p1 < HWSZ) {
                s1 = bias[o];
                #pragma unroll
                for (int q = 0; q < CV_QX; q++) s1 += g_amp[q * QSTR + base + (size_t)p1 * COUT + o];
            }
            esm[o * EM_STRU + j] = pack_h2(s0, s1);
        }
    }

    const float inv = 1.f / (float)HWSZ;

    #pragma unroll 1
    for (int ch = 0; ch < 8; ch++) {
        if (ch + 1 < 8) {
            prefetch_x(ch + 1);
            cp_commit();
            cp_wait<1>();
        } else {
            cp_wait<0>();
        }
        __syncthreads();

        const int arow0 = (32 + 32 * (ch & 1) + mh * 16 + qm) * EM_STRU;
        const int brow0 = (nt * 8 + qm) * EM_STRU;

        float acc[4] = {0.f, 0.f, 0.f, 0.f};
        #pragma unroll
        for (int ks = 0; ks < 13; ks++) {
            const int k0 = ks * 8;
            uint32_t a[4], bf[2];
            a[0] = esm[arow0 + k0 + qk];
            a[1] = esm[arow0 + 8 * EM_STRU + k0 + qk];
            a[2] = esm[arow0 + k0 + 4 + qk];
            a[3] = esm[arow0 + 8 * EM_STRU + k0 + 4 + qk];
            bf[0] = esm[brow0 + k0 + qk];
            bf[1] = esm[brow0 + k0 + 4 + qk];
            mma_f16(acc, a, bf);
        }

        int i = i0 + ch * 32 + mh * 16 + qm;
        int o = nt * 8 + 2 * qk;
        size_t k0h = ((size_t)b * FEAT + (size_t)i * COUT + o) >> 1;
        g_feath[k0h] = pack_h2(acc[0] * inv, acc[1] * inv);
        size_t k1h = ((size_t)b * FEAT + (size_t)(i + 8) * COUT + o) >> 1;
        g_feath[k1h] = pack_h2(acc[2] * inv, acc[3] * inv);
        __syncthreads();
    }
}

// ============================================================
// Kernel 3: fc6 partials, fp16 mma, M=64, 3-stage pipeline, 4 CTAs/SM. (unchanged)
// ============================================================
__global__ void __launch_bounds__(256, 4)
fc6_kernel(const float* __restrict__ w6)
{
    extern __shared__ uint32_t fsm[];
    const uint32_t sb = smem_u32(fsm);

    const int mt  = blockIdx.x;
    const int kt  = blockIdx.y;
    const int tid = threadIdx.x;
    const int wz  = tid >> 5;
    const int lane = tid & 31;
    const int qm = lane >> 2, qk = lane & 3;
    const int mtw = wz >> 1;
    const int nh  = wz & 1;

    const int    mbase = mt * 64;
    const size_t kbase = (size_t)kt * FC6_KPER;

    const int arow = tid >> 2, akoff = (tid & 3) * 8;
    const int brow = tid >> 2, bu = (tid & 3) * 4;
    const float*    ga0 = w6 + (size_t)(mbase + arow) * FEAT + kbase + akoff;
    const uint32_t* gb0 = g_feath + ((size_t)brow * FEAT + kbase) / 2 + bu;

    auto prefetch = [&](int ch) {
        const int st = ch % FC6_NSTG;
        const uint32_t abuf = sb + (uint32_t)st * (STAGE_U32 * 4);
        const uint32_t bbuf = abuf + A_U32 * 4;
        const float* ga = ga0 + (size_t)ch * FC6_KC;
        const uint32_t adst = abuf + (uint32_t)(arow * F6_ASTR + akoff) * 4;
        cp_async16(adst,      ga);
        cp_async16(adst + 16, ga + 4);
        const uint32_t* gb = gb0 + (size_t)ch * (FC6_KC / 2);
        cp_async16(bbuf + (uint32_t)(brow * F6_BSTR + bu) * 4, gb);
    };

    float acc[4][4];
    #pragma unroll
    for (int j = 0; j < 4; j++)
        #pragma unroll
        for (int r = 0; r < 4; r++) acc[j][r] = 0.f;

    prefetch(0); cp_commit();
    prefetch(1); cp_commit();

    #pragma unroll 1
    for (int ch = 0; ch < FC6_NCHUNK; ch++) {
        if (ch + 2 < FC6_NCHUNK) {
            prefetch(ch + 2);
            cp_commit();
            cp_wait<2>();
        } else if (ch + 1 < FC6_NCHUNK) {
            cp_wait<1>();
        } else {
            cp_wait<0>();
        }
        __syncthreads();

        const float*    As = (const float*)(fsm + (ch % FC6_NSTG) * STAGE_U32);
        const uint32_t* Bs = fsm + (ch % FC6_NSTG) * STAGE_U32 + A_U32;
        const int m0 = mtw * 16;

        #pragma unroll
        for (int s = 0; s < 2; s++) {
            const int kb = s * 16;
            uint32_t a[4];
            {
                float2 v0 = *(const float2*)(As + (m0 + qm) * F6_ASTR + kb + 2 * qk);
                float2 v1 = *(const float2*)(As + (m0 + qm + 8) * F6_ASTR + kb + 2 * qk);
                float2 v2 = *(const float2*)(As + (m0 + qm) * F6_ASTR + kb + 8 + 2 * qk);
                float2 v3 = *(const float2*)(As + (m0 + qm + 8) * F6_ASTR + kb + 8 + 2 * qk);
                a[0] = pack_h2(v0.x, v0.y);
                a[1] = pack_h2(v1.x, v1.y);
                a[2] = pack_h2(v2.x, v2.y);
                a[3] = pack_h2(v3.x, v3.y);
            }
            #pragma unroll
            for (int j = 0; j < 4; j++) {
                const int nt = nh * 4 + j;
                uint32_t bf[2];
                bf[0] = Bs[(nt * 8 + qm) * F6_BSTR + s * 8 + qk];
                bf[1] = Bs[(nt * 8 + qm) * F6_BSTR + s * 8 + qk + 4];
                mma_f16(acc[j], a, bf);
            }
        }
        __syncthreads();
    }

    const int r = mbase + mtw * 16 + qm;
    #pragma unroll
    for (int j = 0; j < 4; j++) {
        int bcol = (nh * 4 + j) * 8 + 2 * qk;
        *(float2*)(g_p6 + ((size_t)kt * REP + r) * BB + bcol) =
            make_float2(acc[j][0], acc[j][1]);
        *(float2*)(g_p6 + ((size_t)kt * REP + r + 8) * BB + bcol) =
            make_float2(acc[j][2], acc[j][3]);
    }
}

// ============================================================
// Kernel 4: reduce fc6 partials + bias + relu -> g_h6
// ============================================================
__global__ void __launch_bounds__(256)
reduce6_kernel(const float* __restrict__ b6)
{
    int idx = blockIdx.x * 256 + threadIdx.x;
    int r = idx >> 6, b = idx & 63;
    float sum = b6[r];
    #pragma unroll 8
    for (int kt = 0; kt < FC6_KT; kt++)
        sum += g_p6[((size_t)kt * REP + r) * BB + b];
    g_h6[(size_t)b * REP + r] = fmaxf(sum, 0.f);
}

// ============================================================
// Kernel 5: fc7 + bias + relu. grid (16 bgroups, 4 r-quarters).
// ============================================================
__global__ void __launch_bounds__(256)
fc7_kernel(const float* __restrict__ w7, const float* __restrict__ b7,
           float* __restrict__ out)
{
    const int b0 = blockIdx.x * 4;
    const int r  = blockIdx.y * 256 + threadIdx.x;
    const int tid = threadIdx.x;

    __shared__ float hs[4][REP];
    for (int t = tid; t < 4 * REP; t += 256)
        hs[t >> 10][t & 1023] = g_h6[(size_t)(b0 + (t >> 10)) * REP + (t & 1023)];
    __syncthreads();

    const float4* wr = (const float4*)(w7 + (size_t)r * REP);
    float s0 = 0.f, s1 = 0.f, s2 = 0.f, s3 = 0.f;
    #pragma unroll 4
    for (int k4 = 0; k4 < REP / 4; k4++) {
        float4 wv = wr[k4];
        float4 h0 = *(const float4*)&hs[0][k4 * 4];
        float4 h1 = *(const float4*)&hs[1][k4 * 4];
        float4 h2 = *(const float4*)&hs[2][k4 * 4];
        float4 h3 = *(const float4*)&hs[3][k4 * 4];
        s0 += wv.x * h0.x + wv.y * h0.y + wv.z * h0.z + wv.w * h0.w;
        s1 += wv.x * h1.x + wv.y * h1.y + wv.z * h1.z + wv.w * h1.w;
        s2 += wv.x * h2.x + wv.y * h2.y + wv.z * h2.z + wv.w * h2.w;
        s3 += wv.x * h3.x + wv.y * h3.y + wv.z * h3.z + wv.w * h3.w;
    }
    float bv = b7[r];
    out[(size_t)(b0 + 0) * REP + r] = fmaxf(s0 + bv, 0.f);
    out[(size_t)(b0 + 1) * REP + r] = fmaxf(s1 + bv, 0.f);
    out[(size_t)(b0 + 2) * REP + r] = fmaxf(s2 + bv, 0.f);
    out[(size_t)(b0 + 3) * REP + r] = fmaxf(s3 + bv, 0.f);
}

// ============================================================
// launch (einsum is 4th launch -> profiled)
// ============================================================
extern "C" void kernel_launch(void* const* d_in, const int* in_sizes, int n_in,
                              void* d_out, int out_size)
{
    const float* x      = (const float*)d_in[0];
    const float* conv_w = (const float*)d_in[1];
    const float* conv_b = (const float*)d_in[2];
    const float* w6     = (const float*)d_in[3];
    const float* b6     = (const float*)d_in[4];
    const float* w7     = (const float*)d_in[5];
    const float* b7     = (const float*)d_in[6];
    float* out = (float*)d_out;

    cudaFuncSetAttribute(conv_kernel,   cudaFuncAttributeMaxDynamicSharedMemorySize, CONV_SMEM);
    cudaFuncSetAttribute(einsum_kernel, cudaFuncAttributeMaxDynamicSharedMemorySize, EM_SMEM);
    cudaFuncSetAttribute(fc6_kernel,    cudaFuncAttributeMaxDynamicSharedMemorySize, FC6_SMEM);

    prepw_kernel  <<<dim3(128 * 9 * 8 * 32 / 256), 256>>>(conv_w);
    prepx_kernel  <<<dim3(BB * 128), 256>>>(x);
    conv_kernel   <<<dim3(CV_QX, BB), 256, CONV_SMEM>>>();
    einsum_kernel <<<dim3(8, BB), 256, EM_SMEM>>>(conv_b);
    fc6_kernel    <<<dim3(FC6_MT, FC6_KT), 256, FC6_SMEM>>>(w6);
    reduce6_kernel<<<dim3(BB * REP / 256), 256>>>(b6);
    fc7_kernel    <<<dim3(16, 4), 256>>>(w7, b7, out);
}